// round 1
// baseline (speedup 1.0000x reference)
#include <cuda_runtime.h>
#include <cuda_bf16.h>
#include <math.h>

// Problem constants
#define NN 50000
#define EE 800000
#define ET 850000            // EE + NN self loops
#define HH 4
#define CC1 64
#define HC1 256              // HH*CC1
#define CC2 64
#define HC2 256              // HH*CC2
#define INF_ 128

// ---------------- scratch (device globals; no allocation) ----------------
__device__ float g_h1[(size_t)NN * HC1];     // x @ W1
__device__ float g_h1a[(size_t)NN * HC1];    // elu(layernorm(agg1))
__device__ float g_h2[(size_t)NN * HC2];     // h1a @ W2
__device__ float g_out1[(size_t)NN * HC1];   // layer1 aggregation
__device__ float g_out2[(size_t)NN * HC2];   // layer2 aggregation
__device__ float g_id[(size_t)NN * CC2];     // residual x @ Wres + bres
__device__ float g_w[(size_t)ET * HH];       // per-edge exp weights
__device__ float g_asrc[NN * HH];
__device__ float g_adst[NN * HH];
__device__ float g_s1[NN * HH];
__device__ float g_s2[NN * HH];
__device__ int   g_is64;

// ---------------- edge index dtype detection ----------------
// If edge_index is int64 (little-endian), every odd 32-bit word is 0
// (values < 50000). For int32 data the odd words are random indices,
// so 4096 consecutive zeros is impossible.
__global__ void detect_kernel(const unsigned int* __restrict__ words) {
    __shared__ int any;
    if (threadIdx.x == 0) any = 0;
    __syncthreads();
    for (int i = threadIdx.x; i < 4096; i += blockDim.x) {
        if (words[2 * i + 1] != 0u) any = 1;
    }
    __syncthreads();
    if (threadIdx.x == 0) g_is64 = any ? 0 : 1;
}

__device__ __forceinline__ void load_edge(const void* ei, int e, int& src, int& dst) {
    if (e < EE) {
        if (g_is64) {
            const long long* p = (const long long*)ei;
            src = (int)p[e];
            dst = (int)p[EE + e];
        } else {
            const int* p = (const int*)ei;
            src = p[e];
            dst = p[EE + e];
        }
    } else {
        src = dst = e - EE;
    }
}

// ---------------- zero accumulators ----------------
__global__ void zero_kernel() {
    size_t stride = (size_t)gridDim.x * blockDim.x;
    for (size_t i = blockIdx.x * (size_t)blockDim.x + threadIdx.x;
         i < (size_t)NN * HC1; i += stride) {
        g_out1[i] = 0.f;
        g_out2[i] = 0.f;
    }
    for (size_t i = blockIdx.x * (size_t)blockDim.x + threadIdx.x;
         i < (size_t)NN * HH; i += stride) {
        g_s1[i] = 0.f;
        g_s2[i] = 0.f;
    }
}

// ---------------- SGEMM: C[M,Nc] = A[M,K] @ B[K,Nc] (+bias) ----------------
// BM=BN=64, BK=16, 256 threads, 4x4 per-thread micro-tile.
__global__ __launch_bounds__(256) void sgemm64(
    const float* __restrict__ A, const float* __restrict__ B,
    const float* __restrict__ bias, float* __restrict__ C,
    int M, int Nc, int K)
{
    __shared__ float As[16][68];
    __shared__ float Bs[16][68];
    const int bx = blockIdx.x * 64;
    const int by = blockIdx.y * 64;
    const int tx = threadIdx.x & 15;
    const int ty = threadIdx.x >> 4;

    float acc[4][4] = {};

    for (int k0 = 0; k0 < K; k0 += 16) {
        #pragma unroll
        for (int i = 0; i < 4; i++) {
            int idx = threadIdx.x + i * 256;          // 0..1023
            int m = idx >> 4, k = idx & 15;
            int gm = by + m;
            As[k][m] = (gm < M) ? A[(size_t)gm * K + k0 + k] : 0.f;
            int kk = idx >> 6, n = idx & 63;
            Bs[kk][n] = B[(size_t)(k0 + kk) * Nc + bx + n];
        }
        __syncthreads();
        #pragma unroll
        for (int kk = 0; kk < 16; kk++) {
            float a[4], b[4];
            #pragma unroll
            for (int i = 0; i < 4; i++) a[i] = As[kk][ty * 4 + i];
            #pragma unroll
            for (int j = 0; j < 4; j++) b[j] = Bs[kk][tx * 4 + j];
            #pragma unroll
            for (int i = 0; i < 4; i++)
                #pragma unroll
                for (int j = 0; j < 4; j++)
                    acc[i][j] = fmaf(a[i], b[j], acc[i][j]);
        }
        __syncthreads();
    }

    #pragma unroll
    for (int i = 0; i < 4; i++) {
        int gm = by + ty * 4 + i;
        if (gm >= M) continue;
        #pragma unroll
        for (int j = 0; j < 4; j++) {
            int gn = bx + tx * 4 + j;
            float v = acc[i][j];
            if (bias) v += bias[gn];
            C[(size_t)gm * Nc + gn] = v;
        }
    }
}

// ---------------- per-node attention coefficients ----------------
// one warp per (node, head): asrc[n,h] = dot(h[n,h,:], att_src[h,:])
__global__ __launch_bounds__(256) void alpha_kernel(
    const float* __restrict__ h, const float* __restrict__ att_s,
    const float* __restrict__ att_d, float* __restrict__ asrc,
    float* __restrict__ adst)
{
    int warpId = (blockIdx.x * blockDim.x + threadIdx.x) >> 5;
    int lane = threadIdx.x & 31;
    if (warpId >= NN * HH) return;
    int n = warpId >> 2, hh = warpId & 3;
    const float* hp = h + (size_t)n * 256 + hh * 64;
    float v0 = hp[lane], v1 = hp[lane + 32];
    float s1 = v0 * att_s[hh * 64 + lane] + v1 * att_s[hh * 64 + lane + 32];
    float s2 = v0 * att_d[hh * 64 + lane] + v1 * att_d[hh * 64 + lane + 32];
    #pragma unroll
    for (int o = 16; o; o >>= 1) {
        s1 += __shfl_xor_sync(0xffffffffu, s1, o);
        s2 += __shfl_xor_sync(0xffffffffu, s2, o);
    }
    if (lane == 0) {
        asrc[warpId] = s1;
        adst[warpId] = s2;
    }
}

// ---------------- edge softmax numerator + denominator ----------------
__global__ __launch_bounds__(256) void edge_softmax_kernel(
    const void* __restrict__ ei, const float* __restrict__ asrc,
    const float* __restrict__ adst, float* __restrict__ w,
    float* __restrict__ s)
{
    int tid = blockIdx.x * blockDim.x + threadIdx.x;
    if (tid >= ET * HH) return;
    int e = tid >> 2, hh = tid & 3;
    int src, dst;
    load_edge(ei, e, src, dst);
    float v = asrc[src * 4 + hh] + adst[dst * 4 + hh];
    v = v > 0.f ? v : 0.2f * v;                 // leaky relu
    float wv = __expf(v);
    w[tid] = wv;
    atomicAdd(&s[dst * 4 + hh], wv);
}

// ---------------- weighted scatter-aggregate ----------------
// one 256-thread block per edge: thread t handles feature t (head t/64).
__global__ __launch_bounds__(256) void aggregate_kernel(
    const void* __restrict__ ei, const float* __restrict__ hfeat,
    const float* __restrict__ w, const float* __restrict__ s,
    float* __restrict__ out)
{
    int e = blockIdx.x;
    int tid = threadIdx.x;
    int src, dst;
    load_edge(ei, e, src, dst);
    int hh = tid >> 6;
    float a = __fdividef(w[e * 4 + hh], s[dst * 4 + hh]);
    float v = a * hfeat[(size_t)src * 256 + tid];
    atomicAdd(&out[(size_t)dst * 256 + tid], v);
}

// ---------------- post layer-1: +bias, layernorm(256), elu ----------------
__global__ __launch_bounds__(256) void post1_kernel(
    const float* __restrict__ in, const float* __restrict__ bias,
    const float* __restrict__ g, const float* __restrict__ b,
    float* __restrict__ out)
{
    int warpId = (blockIdx.x * blockDim.x + threadIdx.x) >> 5;
    int lane = threadIdx.x & 31;
    if (warpId >= NN) return;
    const float* p = in + (size_t)warpId * 256;
    float v[8];
    float sum = 0.f;
    #pragma unroll
    for (int i = 0; i < 8; i++) {
        int c = lane + 32 * i;
        v[i] = p[c] + bias[c];
        sum += v[i];
    }
    #pragma unroll
    for (int o = 16; o; o >>= 1) sum += __shfl_xor_sync(0xffffffffu, sum, o);
    float mu = sum * (1.f / 256.f);
    float var = 0.f;
    #pragma unroll
    for (int i = 0; i < 8; i++) {
        float d = v[i] - mu;
        var += d * d;
    }
    #pragma unroll
    for (int o = 16; o; o >>= 1) var += __shfl_xor_sync(0xffffffffu, var, o);
    var *= (1.f / 256.f);
    float rs = rsqrtf(var + 1e-5f);
    float* op = out + (size_t)warpId * 256;
    #pragma unroll
    for (int i = 0; i < 8; i++) {
        int c = lane + 32 * i;
        float y = (v[i] - mu) * rs * g[c] + b[c];
        op[c] = y > 0.f ? y : expm1f(y);        // elu
    }
}

// ---------------- post layer-2: head-mean, +bias, layernorm(64), +res, elu ----------------
__global__ __launch_bounds__(256) void post2_kernel(
    const float* __restrict__ in, const float* __restrict__ bias,
    const float* __restrict__ g, const float* __restrict__ b,
    const float* __restrict__ idn, float* __restrict__ out)
{
    int warpId = (blockIdx.x * blockDim.x + threadIdx.x) >> 5;
    int lane = threadIdx.x & 31;
    if (warpId >= NN) return;
    const float* p = in + (size_t)warpId * 256;
    float v[2];
    float sum = 0.f;
    #pragma unroll
    for (int i = 0; i < 2; i++) {
        int c = lane + 32 * i;
        v[i] = 0.25f * (p[c] + p[64 + c] + p[128 + c] + p[192 + c]) + bias[c];
        sum += v[i];
    }
    #pragma unroll
    for (int o = 16; o; o >>= 1) sum += __shfl_xor_sync(0xffffffffu, sum, o);
    float mu = sum * (1.f / 64.f);
    float var = 0.f;
    #pragma unroll
    for (int i = 0; i < 2; i++) {
        float d = v[i] - mu;
        var += d * d;
    }
    #pragma unroll
    for (int o = 16; o; o >>= 1) var += __shfl_xor_sync(0xffffffffu, var, o);
    var *= (1.f / 64.f);
    float rs = rsqrtf(var + 1e-5f);
    #pragma unroll
    for (int i = 0; i < 2; i++) {
        int c = lane + 32 * i;
        float y = (v[i] - mu) * rs * g[c] + b[c] + idn[(size_t)warpId * 64 + c];
        out[(size_t)warpId * 64 + c] = y > 0.f ? y : expm1f(y);
    }
}

// ---------------- launcher ----------------
extern "C" void kernel_launch(void* const* d_in, const int* in_sizes, int n_in,
                              void* d_out, int out_size) {
    const float* x        = (const float*)d_in[0];
    const void*  ei       = d_in[1];
    const float* W1       = (const float*)d_in[2];
    const float* att_src1 = (const float*)d_in[3];
    const float* att_dst1 = (const float*)d_in[4];
    const float* bias1    = (const float*)d_in[5];
    const float* g1       = (const float*)d_in[6];
    const float* b1       = (const float*)d_in[7];
    const float* W2       = (const float*)d_in[8];
    const float* att_src2 = (const float*)d_in[9];
    const float* att_dst2 = (const float*)d_in[10];
    const float* bias2    = (const float*)d_in[11];
    const float* g2       = (const float*)d_in[12];
    const float* b2       = (const float*)d_in[13];
    const float* Wres     = (const float*)d_in[14];
    const float* bres     = (const float*)d_in[15];
    float* out = (float*)d_out;

    float* p_h1, *p_h1a, *p_h2, *p_out1, *p_out2, *p_id, *p_w, *p_asrc, *p_adst, *p_s1, *p_s2;
    cudaGetSymbolAddress((void**)&p_h1,   g_h1);
    cudaGetSymbolAddress((void**)&p_h1a,  g_h1a);
    cudaGetSymbolAddress((void**)&p_h2,   g_h2);
    cudaGetSymbolAddress((void**)&p_out1, g_out1);
    cudaGetSymbolAddress((void**)&p_out2, g_out2);
    cudaGetSymbolAddress((void**)&p_id,   g_id);
    cudaGetSymbolAddress((void**)&p_w,    g_w);
    cudaGetSymbolAddress((void**)&p_asrc, g_asrc);
    cudaGetSymbolAddress((void**)&p_adst, g_adst);
    cudaGetSymbolAddress((void**)&p_s1,   g_s1);
    cudaGetSymbolAddress((void**)&p_s2,   g_s2);

    // 0) detect edge_index dtype; zero accumulators
    detect_kernel<<<1, 256>>>((const unsigned int*)ei);
    zero_kernel<<<2048, 256>>>();

    dim3 blk(256);

    // 1) residual projection: id = x @ Wres + bres   [N,64]
    {
        dim3 grid(64 / 64, (NN + 63) / 64);
        sgemm64<<<grid, blk>>>(x, Wres, bres, p_id, NN, 64, INF_);
    }
    // 2) layer-1 projection: h1 = x @ W1             [N,256]
    {
        dim3 grid(HC1 / 64, (NN + 63) / 64);
        sgemm64<<<grid, blk>>>(x, W1, nullptr, p_h1, NN, HC1, INF_);
    }
    // 3) attention coefficients
    alpha_kernel<<<(NN * HH + 7) / 8, 256>>>(p_h1, att_src1, att_dst1, p_asrc, p_adst);
    // 4) edge softmax weights + denominators
    edge_softmax_kernel<<<(ET * HH + 255) / 256, 256>>>(ei, p_asrc, p_adst, p_w, p_s1);
    // 5) weighted aggregation
    aggregate_kernel<<<ET, 256>>>(ei, p_h1, p_w, p_s1, p_out1);
    // 6) bias + layernorm + elu
    post1_kernel<<<(NN + 7) / 8, 256>>>(p_out1, bias1, g1, b1, p_h1a);

    // 7) layer-2 projection: h2 = h1a @ W2           [N,256]
    {
        dim3 grid(HC2 / 64, (NN + 63) / 64);
        sgemm64<<<grid, blk>>>(p_h1a, W2, nullptr, p_h2, NN, HC2, HC1);
    }
    // 8) attention coefficients
    alpha_kernel<<<(NN * HH + 7) / 8, 256>>>(p_h2, att_src2, att_dst2, p_asrc, p_adst);
    // 9) edge softmax
    edge_softmax_kernel<<<(ET * HH + 255) / 256, 256>>>(ei, p_asrc, p_adst, p_w, p_s2);
    // 10) aggregation
    aggregate_kernel<<<ET, 256>>>(ei, p_h2, p_w, p_s2, p_out2);
    // 11) head-mean + bias + layernorm + residual + elu -> d_out
    post2_kernel<<<(NN + 7) / 8, 256>>>(p_out2, bias2, g2, b2, p_id, out);
}

// round 2
// speedup vs baseline: 2.5700x; 2.5700x over previous
#include <cuda_runtime.h>
#include <cuda_bf16.h>
#include <math.h>

// Problem constants
#define NN 50000
#define EE 800000
#define ET 850000            // EE + NN self loops
#define HH 4
#define HC1 256
#define CC2 64
#define HC2 256
#define INF_ 128
#define NB 196               // ceil(NN/256)
#define CH 128               // aggregation edge chunk

// ---------------- scratch (device globals; no allocation) ----------------
__device__ float g_h1[(size_t)NN * HC1];     // x @ W1
__device__ float g_h1a[(size_t)NN * HC1];    // elu(layernorm(agg1))
__device__ float g_h2[(size_t)NN * HC2];     // h1a @ W2
__device__ float g_id[(size_t)NN * CC2];     // residual x @ Wres + bres
__device__ float g_asrc[NN * HH];
__device__ float g_adst[NN * HH];
__device__ int   g_deg[NN];
__device__ int   g_row[NN + 1];
__device__ int   g_cursor[NN];
__device__ int   g_csr_src[ET];
__device__ int   g_bsum[NB];
__device__ int   g_boff[NB];
__device__ int   g_is64;

// ---------------- edge index dtype detection ----------------
__global__ void detect_kernel(const unsigned int* __restrict__ words) {
    __shared__ int any;
    if (threadIdx.x == 0) any = 0;
    __syncthreads();
    for (int i = threadIdx.x; i < 4096; i += blockDim.x)
        if (words[2 * i + 1] != 0u) any = 1;
    __syncthreads();
    if (threadIdx.x == 0) g_is64 = any ? 0 : 1;
}

__device__ __forceinline__ void load_edge(const void* ei, int e, int& src, int& dst) {
    if (e < EE) {
        if (g_is64) {
            const long long* p = (const long long*)ei;
            src = (int)p[e];
            dst = (int)p[EE + e];
        } else {
            const int* p = (const int*)ei;
            src = p[e];
            dst = p[EE + e];
        }
    } else {
        src = dst = e - EE;
    }
}

// ---------------- CSR build ----------------
__global__ void zero_deg_kernel() {
    int i = blockIdx.x * blockDim.x + threadIdx.x;
    if (i < NN) g_deg[i] = 0;
}

__global__ void count_kernel(const void* __restrict__ ei) {
    int e = blockIdx.x * blockDim.x + threadIdx.x;
    if (e >= ET) return;
    int s, d;
    load_edge(ei, e, s, d);
    atomicAdd(&g_deg[d], 1);
}

__global__ __launch_bounds__(256) void bsum_kernel() {
    __shared__ int sh[256];
    int i = blockIdx.x * 256 + threadIdx.x;
    sh[threadIdx.x] = (i < NN) ? g_deg[i] : 0;
    __syncthreads();
    for (int o = 128; o; o >>= 1) {
        if (threadIdx.x < o) sh[threadIdx.x] += sh[threadIdx.x + o];
        __syncthreads();
    }
    if (threadIdx.x == 0) g_bsum[blockIdx.x] = sh[0];
}

__global__ __launch_bounds__(256) void bscan_kernel() {
    __shared__ int sh[256];
    int tid = threadIdx.x;
    int v = (tid < NB) ? g_bsum[tid] : 0;
    sh[tid] = v;
    __syncthreads();
    for (int o = 1; o < 256; o <<= 1) {
        int t = 0;
        if (tid >= o) t = sh[tid - o];
        __syncthreads();
        sh[tid] += t;
        __syncthreads();
    }
    if (tid < NB) g_boff[tid] = sh[tid] - v;   // exclusive
    if (tid == 0) g_row[NN] = ET;
}

__global__ __launch_bounds__(256) void rowscan_kernel() {
    __shared__ int sh[256];
    int tid = threadIdx.x;
    int i = blockIdx.x * 256 + tid;
    int v = (i < NN) ? g_deg[i] : 0;
    sh[tid] = v;
    __syncthreads();
    for (int o = 1; o < 256; o <<= 1) {
        int t = 0;
        if (tid >= o) t = sh[tid - o];
        __syncthreads();
        sh[tid] += t;
        __syncthreads();
    }
    if (i < NN) {
        int r = g_boff[blockIdx.x] + sh[tid] - v;
        g_row[i] = r;
        g_cursor[i] = r;
    }
}

__global__ void fill_kernel(const void* __restrict__ ei) {
    int e = blockIdx.x * blockDim.x + threadIdx.x;
    if (e >= ET) return;
    int s, d;
    load_edge(ei, e, s, d);
    int pos = atomicAdd(&g_cursor[d], 1);
    g_csr_src[pos] = s;
}

// ---------------- SGEMM 128x64x8, float4 smem reads ----------------
__global__ __launch_bounds__(256) void sgemm128(
    const float* __restrict__ A, const float* __restrict__ B,
    const float* __restrict__ bias, float* __restrict__ C,
    int M, int Nc, int K)
{
    __shared__ __align__(16) float As[8][132];   // 132*4 = 528 = 16*33
    __shared__ __align__(16) float Bs[8][68];    // 68*4  = 272 = 16*17
    const int bx = blockIdx.x * 64;
    const int by = blockIdx.y * 128;
    const int tx = threadIdx.x & 15;
    const int ty = threadIdx.x >> 4;

    float acc[8][4] = {};

    for (int k0 = 0; k0 < K; k0 += 8) {
        #pragma unroll
        for (int i = 0; i < 4; i++) {
            int idx = threadIdx.x + i * 256;          // 0..1023
            int m = idx >> 3, k = idx & 7;
            int gm = by + m;
            As[k][m] = (gm < M) ? A[(size_t)gm * K + k0 + k] : 0.f;
        }
        #pragma unroll
        for (int i = 0; i < 2; i++) {
            int idx = threadIdx.x + i * 256;          // 0..511
            int kk = idx >> 6, n = idx & 63;
            Bs[kk][n] = B[(size_t)(k0 + kk) * Nc + bx + n];
        }
        __syncthreads();
        #pragma unroll
        for (int kk = 0; kk < 8; kk++) {
            float4 a0 = *(const float4*)&As[kk][ty * 8];
            float4 a1 = *(const float4*)&As[kk][ty * 8 + 4];
            float4 b0 = *(const float4*)&Bs[kk][tx * 4];
            float a[8] = {a0.x, a0.y, a0.z, a0.w, a1.x, a1.y, a1.z, a1.w};
            float bb[4] = {b0.x, b0.y, b0.z, b0.w};
            #pragma unroll
            for (int i = 0; i < 8; i++)
                #pragma unroll
                for (int j = 0; j < 4; j++)
                    acc[i][j] = fmaf(a[i], bb[j], acc[i][j]);
        }
        __syncthreads();
    }

    float4 bv = make_float4(0.f, 0.f, 0.f, 0.f);
    if (bias) bv = *(const float4*)&bias[bx + tx * 4];
    #pragma unroll
    for (int i = 0; i < 8; i++) {
        int gm = by + ty * 8 + i;
        if (gm >= M) continue;
        float4 o;
        o.x = acc[i][0] + bv.x;
        o.y = acc[i][1] + bv.y;
        o.z = acc[i][2] + bv.z;
        o.w = acc[i][3] + bv.w;
        *(float4*)&C[(size_t)gm * Nc + bx + tx * 4] = o;
    }
}

// ---------------- per-node attention coefficients ----------------
__global__ __launch_bounds__(256) void alpha_kernel(
    const float* __restrict__ h, const float* __restrict__ att_s,
    const float* __restrict__ att_d, float* __restrict__ asrc,
    float* __restrict__ adst)
{
    int warpId = (blockIdx.x * blockDim.x + threadIdx.x) >> 5;
    int lane = threadIdx.x & 31;
    if (warpId >= NN * HH) return;
    int n = warpId >> 2, hh = warpId & 3;
    const float* hp = h + (size_t)n * 256 + hh * 64;
    float v0 = hp[lane], v1 = hp[lane + 32];
    float s1 = v0 * att_s[hh * 64 + lane] + v1 * att_s[hh * 64 + lane + 32];
    float s2 = v0 * att_d[hh * 64 + lane] + v1 * att_d[hh * 64 + lane + 32];
    #pragma unroll
    for (int o = 16; o; o >>= 1) {
        s1 += __shfl_xor_sync(0xffffffffu, s1, o);
        s2 += __shfl_xor_sync(0xffffffffu, s2, o);
    }
    if (lane == 0) {
        asrc[warpId] = s1;
        adst[warpId] = s2;
    }
}

// ---------------- fused CSR aggregation core ----------------
// Each block handles one dst node; thread tid owns feature column tid
// (head h = tid>>6). Returns the normalized aggregated value per thread.
__device__ __forceinline__ float aggregate_node(
    int n, int tid, const float* __restrict__ hfeat,
    const float* __restrict__ asrc, const float* __restrict__ adst,
    float* s4, int* ssrc, float* sa)
{
    int r0 = g_row[n], r1 = g_row[n + 1];
    int deg = r1 - r0;
    if (tid < 4) s4[tid] = 0.f;
    __syncthreads();

    // pass 1: softmax denominator per head
    float part[1];
    (void)part;
    for (int idx = tid; idx < deg * 4; idx += 256) {
        int j = idx >> 2, hh = idx & 3;
        int src = g_csr_src[r0 + j];
        float v = asrc[src * 4 + hh] + adst[n * 4 + hh];
        v = v > 0.f ? v : 0.2f * v;
        atomicAdd(&s4[hh], __expf(v));
    }

    int h = tid >> 6;
    float acc = 0.f;
    for (int c0 = 0; c0 < deg; c0 += CH) {
        int cnt = min(CH, deg - c0);
        __syncthreads();
        for (int idx = tid; idx < cnt * 4; idx += 256) {
            int j = idx >> 2, hh = idx & 3;
            int src = g_csr_src[r0 + c0 + j];
            if (hh == 0) ssrc[j] = src;
            float v = asrc[src * 4 + hh] + adst[n * 4 + hh];
            v = v > 0.f ? v : 0.2f * v;
            sa[j * 4 + hh] = __expf(v);
        }
        __syncthreads();
        int j = 0;
        for (; j + 4 <= cnt; j += 4) {
            int s0 = ssrc[j], s1_ = ssrc[j + 1], s2_ = ssrc[j + 2], s3 = ssrc[j + 3];
            float w0 = sa[(j) * 4 + h], w1 = sa[(j + 1) * 4 + h];
            float w2 = sa[(j + 2) * 4 + h], w3 = sa[(j + 3) * 4 + h];
            float f0 = hfeat[(size_t)s0 * 256 + tid];
            float f1 = hfeat[(size_t)s1_ * 256 + tid];
            float f2 = hfeat[(size_t)s2_ * 256 + tid];
            float f3 = hfeat[(size_t)s3 * 256 + tid];
            acc = fmaf(w0, f0, acc);
            acc = fmaf(w1, f1, acc);
            acc = fmaf(w2, f2, acc);
            acc = fmaf(w3, f3, acc);
        }
        for (; j < cnt; j++)
            acc = fmaf(sa[j * 4 + h], hfeat[(size_t)ssrc[j] * 256 + tid], acc);
    }
    return acc * (1.f / s4[h]);
}

// ---------------- layer 1: aggregate + bias + LN(256) + ELU ----------------
__global__ __launch_bounds__(256) void agg1_kernel(
    const float* __restrict__ hfeat, const float* __restrict__ asrc,
    const float* __restrict__ adst, const float* __restrict__ bias,
    const float* __restrict__ g, const float* __restrict__ b,
    float* __restrict__ out)
{
    __shared__ float s4[4];
    __shared__ int   ssrc[CH];
    __shared__ float sa[CH * 4];
    __shared__ float red[8];
    int n = blockIdx.x;
    int tid = threadIdx.x;
    int lane = tid & 31, wid = tid >> 5;

    float v = aggregate_node(n, tid, hfeat, asrc, adst, s4, ssrc, sa) + bias[tid];

    // mean
    float t = v;
    #pragma unroll
    for (int o = 16; o; o >>= 1) t += __shfl_xor_sync(0xffffffffu, t, o);
    if (lane == 0) red[wid] = t;
    __syncthreads();
    float mu = 0.f;
    #pragma unroll
    for (int i = 0; i < 8; i++) mu += red[i];
    mu *= (1.f / 256.f);
    __syncthreads();
    // var
    float d = v - mu;
    t = d * d;
    #pragma unroll
    for (int o = 16; o; o >>= 1) t += __shfl_xor_sync(0xffffffffu, t, o);
    if (lane == 0) red[wid] = t;
    __syncthreads();
    float var = 0.f;
    #pragma unroll
    for (int i = 0; i < 8; i++) var += red[i];
    var *= (1.f / 256.f);
    float rs = rsqrtf(var + 1e-5f);

    float y = d * rs * g[tid] + b[tid];
    out[(size_t)n * 256 + tid] = y > 0.f ? y : expm1f(y);
}

// ---------- layer 2: aggregate + head-mean + bias + LN(64) + res + ELU ----------
__global__ __launch_bounds__(256) void agg2_kernel(
    const float* __restrict__ hfeat, const float* __restrict__ asrc,
    const float* __restrict__ adst, const float* __restrict__ bias,
    const float* __restrict__ g, const float* __restrict__ b,
    const float* __restrict__ idn, float* __restrict__ out)
{
    __shared__ float s4[4];
    __shared__ int   ssrc[CH];
    __shared__ float sa[CH * 4];
    __shared__ float shv[256];
    __shared__ float red[8];
    int n = blockIdx.x;
    int tid = threadIdx.x;
    int lane = tid & 31;

    float acc = aggregate_node(n, tid, hfeat, asrc, adst, s4, ssrc, sa);
    shv[tid] = acc;
    __syncthreads();

    float m = 0.f;
    if (tid < 64)
        m = 0.25f * (shv[tid] + shv[tid + 64] + shv[tid + 128] + shv[tid + 192]) + bias[tid];

    // mean over 64 (warps 0,1)
    float t = m;
    #pragma unroll
    for (int o = 16; o; o >>= 1) t += __shfl_xor_sync(0xffffffffu, t, o);
    if (lane == 0 && tid < 64) red[tid >> 5] = t;
    __syncthreads();
    float mu = (red[0] + red[1]) * (1.f / 64.f);
    __syncthreads();
    float d = m - mu;
    t = d * d;
    #pragma unroll
    for (int o = 16; o; o >>= 1) t += __shfl_xor_sync(0xffffffffu, t, o);
    if (lane == 0 && tid < 64) red[4 + (tid >> 5)] = t;
    __syncthreads();
    float var = (red[4] + red[5]) * (1.f / 64.f);
    float rs = rsqrtf(var + 1e-5f);

    if (tid < 64) {
        float y = d * rs * g[tid] + b[tid] + idn[(size_t)n * 64 + tid];
        out[(size_t)n * 64 + tid] = y > 0.f ? y : expm1f(y);
    }
}

// ---------------- launcher ----------------
extern "C" void kernel_launch(void* const* d_in, const int* in_sizes, int n_in,
                              void* d_out, int out_size) {
    const float* x        = (const float*)d_in[0];
    const void*  ei       = d_in[1];
    const float* W1       = (const float*)d_in[2];
    const float* att_src1 = (const float*)d_in[3];
    const float* att_dst1 = (const float*)d_in[4];
    const float* bias1    = (const float*)d_in[5];
    const float* g1       = (const float*)d_in[6];
    const float* b1       = (const float*)d_in[7];
    const float* W2       = (const float*)d_in[8];
    const float* att_src2 = (const float*)d_in[9];
    const float* att_dst2 = (const float*)d_in[10];
    const float* bias2    = (const float*)d_in[11];
    const float* g2       = (const float*)d_in[12];
    const float* b2       = (const float*)d_in[13];
    const float* Wres     = (const float*)d_in[14];
    const float* bres     = (const float*)d_in[15];
    float* out = (float*)d_out;

    float *p_h1, *p_h1a, *p_h2, *p_id, *p_asrc, *p_adst;
    cudaGetSymbolAddress((void**)&p_h1,   g_h1);
    cudaGetSymbolAddress((void**)&p_h1a,  g_h1a);
    cudaGetSymbolAddress((void**)&p_h2,   g_h2);
    cudaGetSymbolAddress((void**)&p_id,   g_id);
    cudaGetSymbolAddress((void**)&p_asrc, g_asrc);
    cudaGetSymbolAddress((void**)&p_adst, g_adst);

    dim3 blk(256);

    // CSR build (dtype detect -> degree count -> scan -> fill)
    detect_kernel<<<1, 256>>>((const unsigned int*)ei);
    zero_deg_kernel<<<NB, 256>>>();
    count_kernel<<<(ET + 255) / 256, 256>>>(ei);
    bsum_kernel<<<NB, 256>>>();
    bscan_kernel<<<1, 256>>>();
    rowscan_kernel<<<NB, 256>>>();
    fill_kernel<<<(ET + 255) / 256, 256>>>(ei);

    // residual projection: id = x @ Wres + bres  [N,64]
    {
        dim3 grid(1, (NN + 127) / 128);
        sgemm128<<<grid, blk>>>(x, Wres, bres, p_id, NN, 64, INF_);
    }
    // layer-1 projection: h1 = x @ W1  [N,256]
    {
        dim3 grid(HC1 / 64, (NN + 127) / 128);
        sgemm128<<<grid, blk>>>(x, W1, nullptr, p_h1, NN, HC1, INF_);
    }
    alpha_kernel<<<(NN * HH + 7) / 8, 256>>>(p_h1, att_src1, att_dst1, p_asrc, p_adst);
    agg1_kernel<<<NN, 256>>>(p_h1, p_asrc, p_adst, bias1, g1, b1, p_h1a);

    // layer-2 projection: h2 = h1a @ W2  [N,256]
    {
        dim3 grid(HC2 / 64, (NN + 127) / 128);
        sgemm128<<<grid, blk>>>(p_h1a, W2, nullptr, p_h2, NN, HC2, HC1);
    }
    alpha_kernel<<<(NN * HH + 7) / 8, 256>>>(p_h2, att_src2, att_dst2, p_asrc, p_adst);
    agg2_kernel<<<NN, 256>>>(p_h2, p_asrc, p_adst, bias2, g2, b2, p_id, out);
}

// round 3
// speedup vs baseline: 2.6987x; 1.0501x over previous
#include <cuda_runtime.h>
#include <cuda_bf16.h>
#include <math.h>

// Problem constants
#define NN 50000
#define EE 800000
#define ET 850000            // EE + NN self loops
#define HH 4
#define HC1 256
#define CC2 64
#define HC2 256
#define INF_ 128
#define NB 196               // ceil(NN/256)
#define CH 128               // aggregation edge chunk

// ---------------- scratch (device globals; no allocation) ----------------
__device__ float g_h1[(size_t)NN * HC1];     // x @ W1
__device__ float g_h1a[(size_t)NN * HC1];    // elu(layernorm(agg1))
__device__ float g_h2[(size_t)NN * HC2];     // h1a @ W2
__device__ float g_id[(size_t)NN * CC2];     // residual x @ Wres + bres
__device__ float g_asrc[NN * HH];
__device__ float g_adst[NN * HH];
__device__ int   g_deg[NN];
__device__ int   g_row[NN + 1];
__device__ int   g_cursor[NN];
__device__ int   g_csr_src[ET];
__device__ int   g_bsum[NB];
__device__ int   g_boff[NB];
__device__ int   g_is64;

// ---------------- edge index dtype detection ----------------
__global__ void detect_kernel(const unsigned int* __restrict__ words) {
    __shared__ int any;
    if (threadIdx.x == 0) any = 0;
    __syncthreads();
    for (int i = threadIdx.x; i < 4096; i += blockDim.x)
        if (words[2 * i + 1] != 0u) any = 1;
    __syncthreads();
    if (threadIdx.x == 0) g_is64 = any ? 0 : 1;
}

__device__ __forceinline__ void load_edge(const void* ei, int e, int& src, int& dst) {
    if (e < EE) {
        if (g_is64) {
            const long long* p = (const long long*)ei;
            src = (int)p[e];
            dst = (int)p[EE + e];
        } else {
            const int* p = (const int*)ei;
            src = p[e];
            dst = p[EE + e];
        }
    } else {
        src = dst = e - EE;
    }
}

// ---------------- CSR build ----------------
__global__ void zero_deg_kernel() {
    int i = blockIdx.x * blockDim.x + threadIdx.x;
    if (i < NN) g_deg[i] = 0;
}

__global__ void count_kernel(const void* __restrict__ ei) {
    int e = blockIdx.x * blockDim.x + threadIdx.x;
    if (e >= ET) return;
    int s, d;
    load_edge(ei, e, s, d);
    atomicAdd(&g_deg[d], 1);
}

__global__ __launch_bounds__(256) void bsum_kernel() {
    __shared__ int sh[256];
    int i = blockIdx.x * 256 + threadIdx.x;
    sh[threadIdx.x] = (i < NN) ? g_deg[i] : 0;
    __syncthreads();
    for (int o = 128; o; o >>= 1) {
        if (threadIdx.x < o) sh[threadIdx.x] += sh[threadIdx.x + o];
        __syncthreads();
    }
    if (threadIdx.x == 0) g_bsum[blockIdx.x] = sh[0];
}

__global__ __launch_bounds__(256) void bscan_kernel() {
    __shared__ int sh[256];
    int tid = threadIdx.x;
    int v = (tid < NB) ? g_bsum[tid] : 0;
    sh[tid] = v;
    __syncthreads();
    for (int o = 1; o < 256; o <<= 1) {
        int t = 0;
        if (tid >= o) t = sh[tid - o];
        __syncthreads();
        sh[tid] += t;
        __syncthreads();
    }
    if (tid < NB) g_boff[tid] = sh[tid] - v;   // exclusive
    if (tid == 0) g_row[NN] = ET;
}

__global__ __launch_bounds__(256) void rowscan_kernel() {
    __shared__ int sh[256];
    int tid = threadIdx.x;
    int i = blockIdx.x * 256 + tid;
    int v = (i < NN) ? g_deg[i] : 0;
    sh[tid] = v;
    __syncthreads();
    for (int o = 1; o < 256; o <<= 1) {
        int t = 0;
        if (tid >= o) t = sh[tid - o];
        __syncthreads();
        sh[tid] += t;
        __syncthreads();
    }
    if (i < NN) {
        int r = g_boff[blockIdx.x] + sh[tid] - v;
        g_row[i] = r;
        g_cursor[i] = r;
    }
}

__global__ void fill_kernel(const void* __restrict__ ei) {
    int e = blockIdx.x * blockDim.x + threadIdx.x;
    if (e >= ET) return;
    int s, d;
    load_edge(ei, e, s, d);
    int pos = atomicAdd(&g_cursor[d], 1);
    g_csr_src[pos] = s;
}

// ---------------- SGEMM 128x128x8, 8x8 micro-tile ----------------
__global__ __launch_bounds__(256) void sgemmTT(
    const float* __restrict__ A, const float* __restrict__ B,
    float* __restrict__ C, int M, int Nc, int K)
{
    __shared__ __align__(16) float As[8][132];
    __shared__ __align__(16) float Bs[8][128];
    const int bx = blockIdx.x * 128;
    const int by = blockIdx.y * 128;
    const int tx = threadIdx.x & 15;
    const int ty = threadIdx.x >> 4;
    const int t  = threadIdx.x;

    float acc[8][8] = {};

    for (int k0 = 0; k0 < K; k0 += 8) {
        // A tile: 128 rows x 8 k -> 256 float4 loads (t>>1 = row, t&1 = half)
        {
            int m = t >> 1, c = (t & 1) * 4;
            int gm = by + m;
            float4 av = make_float4(0.f, 0.f, 0.f, 0.f);
            if (gm < M) av = *(const float4*)&A[(size_t)gm * K + k0 + c];
            As[c + 0][m] = av.x;
            As[c + 1][m] = av.y;
            As[c + 2][m] = av.z;
            As[c + 3][m] = av.w;
        }
        // B tile: 8 k x 128 n -> 256 float4 loads
        {
            int kk = t >> 5, n4 = t & 31;
            float4 bv = *(const float4*)&B[(size_t)(k0 + kk) * Nc + bx + n4 * 4];
            *(float4*)&Bs[kk][n4 * 4] = bv;
        }
        __syncthreads();
        #pragma unroll
        for (int kk = 0; kk < 8; kk++) {
            float4 a0 = *(const float4*)&As[kk][ty * 8];
            float4 a1 = *(const float4*)&As[kk][ty * 8 + 4];
            float4 b0 = *(const float4*)&Bs[kk][tx * 8];
            float4 b1 = *(const float4*)&Bs[kk][tx * 8 + 4];
            float a[8] = {a0.x, a0.y, a0.z, a0.w, a1.x, a1.y, a1.z, a1.w};
            float b[8] = {b0.x, b0.y, b0.z, b0.w, b1.x, b1.y, b1.z, b1.w};
            #pragma unroll
            for (int i = 0; i < 8; i++)
                #pragma unroll
                for (int j = 0; j < 8; j++)
                    acc[i][j] = fmaf(a[i], b[j], acc[i][j]);
        }
        __syncthreads();
    }

    #pragma unroll
    for (int i = 0; i < 8; i++) {
        int gm = by + ty * 8 + i;
        if (gm >= M) continue;
        float4 o0 = make_float4(acc[i][0], acc[i][1], acc[i][2], acc[i][3]);
        float4 o1 = make_float4(acc[i][4], acc[i][5], acc[i][6], acc[i][7]);
        *(float4*)&C[(size_t)gm * Nc + bx + tx * 8]     = o0;
        *(float4*)&C[(size_t)gm * Nc + bx + tx * 8 + 4] = o1;
    }
}

// ---------------- SGEMM 128x64 (residual, Nc=64) ----------------
__global__ __launch_bounds__(256) void sgemm128(
    const float* __restrict__ A, const float* __restrict__ B,
    const float* __restrict__ bias, float* __restrict__ C,
    int M, int Nc, int K)
{
    __shared__ __align__(16) float As[8][132];
    __shared__ __align__(16) float Bs[8][68];
    const int bx = blockIdx.x * 64;
    const int by = blockIdx.y * 128;
    const int tx = threadIdx.x & 15;
    const int ty = threadIdx.x >> 4;

    float acc[8][4] = {};

    for (int k0 = 0; k0 < K; k0 += 8) {
        #pragma unroll
        for (int i = 0; i < 4; i++) {
            int idx = threadIdx.x + i * 256;
            int m = idx >> 3, k = idx & 7;
            int gm = by + m;
            As[k][m] = (gm < M) ? A[(size_t)gm * K + k0 + k] : 0.f;
        }
        #pragma unroll
        for (int i = 0; i < 2; i++) {
            int idx = threadIdx.x + i * 256;
            int kk = idx >> 6, n = idx & 63;
            Bs[kk][n] = B[(size_t)(k0 + kk) * Nc + bx + n];
        }
        __syncthreads();
        #pragma unroll
        for (int kk = 0; kk < 8; kk++) {
            float4 a0 = *(const float4*)&As[kk][ty * 8];
            float4 a1 = *(const float4*)&As[kk][ty * 8 + 4];
            float4 b0 = *(const float4*)&Bs[kk][tx * 4];
            float a[8] = {a0.x, a0.y, a0.z, a0.w, a1.x, a1.y, a1.z, a1.w};
            float bb[4] = {b0.x, b0.y, b0.z, b0.w};
            #pragma unroll
            for (int i = 0; i < 8; i++)
                #pragma unroll
                for (int j = 0; j < 4; j++)
                    acc[i][j] = fmaf(a[i], bb[j], acc[i][j]);
        }
        __syncthreads();
    }

    float4 bv = make_float4(0.f, 0.f, 0.f, 0.f);
    if (bias) bv = *(const float4*)&bias[bx + tx * 4];
    #pragma unroll
    for (int i = 0; i < 8; i++) {
        int gm = by + ty * 8 + i;
        if (gm >= M) continue;
        float4 o;
        o.x = acc[i][0] + bv.x;
        o.y = acc[i][1] + bv.y;
        o.z = acc[i][2] + bv.z;
        o.w = acc[i][3] + bv.w;
        *(float4*)&C[(size_t)gm * Nc + bx + tx * 4] = o;
    }
}

// ---------------- per-node attention coefficients ----------------
__global__ __launch_bounds__(256) void alpha_kernel(
    const float* __restrict__ h, const float* __restrict__ att_s,
    const float* __restrict__ att_d, float* __restrict__ asrc,
    float* __restrict__ adst)
{
    int warpId = (blockIdx.x * blockDim.x + threadIdx.x) >> 5;
    int lane = threadIdx.x & 31;
    if (warpId >= NN * HH) return;
    int n = warpId >> 2, hh = warpId & 3;
    const float* hp = h + (size_t)n * 256 + hh * 64;
    float v0 = hp[lane], v1 = hp[lane + 32];
    float s1 = v0 * att_s[hh * 64 + lane] + v1 * att_s[hh * 64 + lane + 32];
    float s2 = v0 * att_d[hh * 64 + lane] + v1 * att_d[hh * 64 + lane + 32];
    #pragma unroll
    for (int o = 16; o; o >>= 1) {
        s1 += __shfl_xor_sync(0xffffffffu, s1, o);
        s2 += __shfl_xor_sync(0xffffffffu, s2, o);
    }
    if (lane == 0) {
        asrc[warpId] = s1;
        adst[warpId] = s2;
    }
}

// ---------------- fused CSR aggregation core (single pass) ----------------
// Layout: el = tid>>6 (edge slot 0..3), q = tid&63 (float4 feature quad,
// head h = q>>4). Each thread accumulates acc4 over edges j = el, el+4, ...
// Weights computed once per (edge, head) into shared; denominator partials
// accumulated in registers (head = tid&3) and reduced at the end.
// After this returns, shv4[256] holds per-slot partial float4s and s4[4]
// holds the per-head softmax denominators. Caller must __syncthreads() then
// combine slots.
__device__ __forceinline__ void aggregate_node(
    int n, int tid, const float* __restrict__ hfeat,
    const float* __restrict__ asrc, const float* __restrict__ adst,
    float* s4, float* sadst, int* ssrc, float* sa, float4* shv4,
    float* sred)
{
    int r0 = g_row[n], r1 = g_row[n + 1];
    int deg = r1 - r0;
    if (tid < 4) sadst[tid] = adst[n * 4 + tid];
    __syncthreads();

    const int el = tid >> 6;
    const int q  = tid & 63;
    const int h  = q >> 4;
    float4 acc = make_float4(0.f, 0.f, 0.f, 0.f);
    float dpart = 0.f;                       // partial denominator, head tid&3

    for (int c0 = 0; c0 < deg; c0 += CH) {
        int cnt = min(CH, deg - c0);
        __syncthreads();
        for (int idx = tid; idx < cnt * 4; idx += 256) {
            int j = idx >> 2, hh = idx & 3;
            int src = g_csr_src[r0 + c0 + j];
            if (hh == 0) ssrc[j] = src;
            float v = asrc[src * 4 + hh] + sadst[hh];
            v = v > 0.f ? v : 0.2f * v;
            float w = __expf(v);
            sa[j * 4 + hh] = w;
            dpart += w;
        }
        __syncthreads();
        for (int j = el; j < cnt; j += 4) {
            int src = ssrc[j];
            float w = sa[j * 4 + h];
            float4 f = *(const float4*)&hfeat[(size_t)src * 256 + q * 4];
            acc.x = fmaf(w, f.x, acc.x);
            acc.y = fmaf(w, f.y, acc.y);
            acc.z = fmaf(w, f.z, acc.z);
            acc.w = fmaf(w, f.w, acc.w);
        }
    }

    shv4[tid] = acc;
    // reduce denominators: each thread's dpart belongs to head tid&3
    #pragma unroll
    for (int o = 4; o < 32; o <<= 1)
        dpart += __shfl_xor_sync(0xffffffffu, dpart, o);
    int lane = tid & 31, wid = tid >> 5;
    if (lane < 4) sred[wid * 4 + lane] = dpart;
    __syncthreads();
    if (tid < 4) {
        float s = 0.f;
        #pragma unroll
        for (int i = 0; i < 8; i++) s += sred[i * 4 + tid];
        s4[tid] = 1.f / s;
    }
}

// ---------------- layer 1: aggregate + bias + LN(256) + ELU ----------------
__global__ __launch_bounds__(256) void agg1_kernel(
    const float* __restrict__ hfeat, const float* __restrict__ asrc,
    const float* __restrict__ adst, const float* __restrict__ bias,
    const float* __restrict__ g, const float* __restrict__ b,
    float* __restrict__ out)
{
    __shared__ float  s4[4];
    __shared__ float  sadst[4];
    __shared__ int    ssrc[CH];
    __shared__ float  sa[CH * 4];
    __shared__ __align__(16) float4 shv4[256];
    __shared__ float  sred[32];
    __shared__ float  red2[4];
    int n = blockIdx.x;
    int tid = threadIdx.x;

    aggregate_node(n, tid, hfeat, asrc, adst, s4, sadst, ssrc, sa, shv4, sred);
    __syncthreads();

    if (tid < 64) {
        int h = tid >> 4;
        float4 v0 = shv4[tid], v1 = shv4[64 + tid], v2 = shv4[128 + tid], v3 = shv4[192 + tid];
        float sc = s4[h];
        float4 bv = *(const float4*)&bias[tid * 4];
        float4 v;
        v.x = (v0.x + v1.x + v2.x + v3.x) * sc + bv.x;
        v.y = (v0.y + v1.y + v2.y + v3.y) * sc + bv.y;
        v.z = (v0.z + v1.z + v2.z + v3.z) * sc + bv.z;
        v.w = (v0.w + v1.w + v2.w + v3.w) * sc + bv.w;

        // LN over 256 features held by 64 threads (warps 0,1)
        float t = v.x + v.y + v.z + v.w;
        #pragma unroll
        for (int o = 16; o; o >>= 1) t += __shfl_xor_sync(0xffffffffu, t, o);
        int lane = tid & 31;
        if (lane == 0) red2[tid >> 5] = t;
        __syncwarp();
        // combine two warps via shared; need both warps' writes visible
        __threadfence_block();
        // simple spin-free: both warps re-read after a barrier among 64 threads
        // (use shfl trick: warps 0,1 both reached here; a block-wide sync is
        // safe since threads >=64 are idle-waiting at the final sync below)
        // -> use named barrier via __syncthreads-free path: do a cheap
        // full-block sync instead.
        // (fallthrough handled below)
        shv4[tid].x = v.x; shv4[tid].y = v.y; shv4[tid].z = v.z; shv4[tid].w = v.w;
    }
    __syncthreads();
    if (tid < 64) {
        float4 v = shv4[tid];
        float mu = (red2[0] + red2[1]) * (1.f / 256.f);
        float dx = v.x - mu, dy = v.y - mu, dz = v.z - mu, dw = v.w - mu;
        float t = dx * dx + dy * dy + dz * dz + dw * dw;
        #pragma unroll
        for (int o = 16; o; o >>= 1) t += __shfl_xor_sync(0xffffffffu, t, o);
        int lane = tid & 31;
        if (lane == 0) red2[2 + (tid >> 5)] = t;
    }
    __syncthreads();
    if (tid < 64) {
        float4 v = shv4[tid];
        float mu = (red2[0] + red2[1]) * (1.f / 256.f);
        float var = (red2[2] + red2[3]) * (1.f / 256.f);
        float rs = rsqrtf(var + 1e-5f);
        float4 gv = *(const float4*)&g[tid * 4];
        float4 bv = *(const float4*)&b[tid * 4];
        float4 y;
        y.x = (v.x - mu) * rs * gv.x + bv.x;
        y.y = (v.y - mu) * rs * gv.y + bv.y;
        y.z = (v.z - mu) * rs * gv.z + bv.z;
        y.w = (v.w - mu) * rs * gv.w + bv.w;
        y.x = y.x > 0.f ? y.x : expm1f(y.x);
        y.y = y.y > 0.f ? y.y : expm1f(y.y);
        y.z = y.z > 0.f ? y.z : expm1f(y.z);
        y.w = y.w > 0.f ? y.w : expm1f(y.w);
        *(float4*)&out[(size_t)n * 256 + tid * 4] = y;
    }
}

// ---------- layer 2: aggregate + head-mean + bias + LN(64) + res + ELU ----------
__global__ __launch_bounds__(256) void agg2_kernel(
    const float* __restrict__ hfeat, const float* __restrict__ asrc,
    const float* __restrict__ adst, const float* __restrict__ bias,
    const float* __restrict__ g, const float* __restrict__ b,
    const float* __restrict__ idn, float* __restrict__ out)
{
    __shared__ float  s4[4];
    __shared__ float  sadst[4];
    __shared__ int    ssrc[CH];
    __shared__ float  sa[CH * 4];
    __shared__ __align__(16) float4 shv4[256];
    __shared__ float  sred[32];
    int n = blockIdx.x;
    int tid = threadIdx.x;

    aggregate_node(n, tid, hfeat, asrc, adst, s4, sadst, ssrc, sa, shv4, sred);
    __syncthreads();

    // combine 4 edge slots into 64 quads (scaled per head)
    if (tid < 64) {
        int h = tid >> 4;
        float4 v0 = shv4[tid], v1 = shv4[64 + tid], v2 = shv4[128 + tid], v3 = shv4[192 + tid];
        float sc = s4[h];
        float4 v;
        v.x = (v0.x + v1.x + v2.x + v3.x) * sc;
        v.y = (v0.y + v1.y + v2.y + v3.y) * sc;
        v.z = (v0.z + v1.z + v2.z + v3.z) * sc;
        v.w = (v0.w + v1.w + v2.w + v3.w) * sc;
        shv4[tid] = v;
    }
    __syncthreads();

    // head mean: output quad p (features 4p..4p+3) = mean over quads p,p+16,p+32,p+48
    if (tid < 16) {
        float4 v0 = shv4[tid], v1 = shv4[tid + 16], v2 = shv4[tid + 32], v3 = shv4[tid + 48];
        float4 bv = *(const float4*)&bias[tid * 4];
        float4 m;
        m.x = 0.25f * (v0.x + v1.x + v2.x + v3.x) + bv.x;
        m.y = 0.25f * (v0.y + v1.y + v2.y + v3.y) + bv.y;
        m.z = 0.25f * (v0.z + v1.z + v2.z + v3.z) + bv.z;
        m.w = 0.25f * (v0.w + v1.w + v2.w + v3.w) + bv.w;

        // LN over 64 among 16 lanes of warp 0
        float t = m.x + m.y + m.z + m.w;
        #pragma unroll
        for (int o = 1; o < 16; o <<= 1) t += __shfl_xor_sync(0xffffu, t, o);
        float mu = t * (1.f / 64.f);
        float dx = m.x - mu, dy = m.y - mu, dz = m.z - mu, dw = m.w - mu;
        float t2 = dx * dx + dy * dy + dz * dz + dw * dw;
        #pragma unroll
        for (int o = 1; o < 16; o <<= 1) t2 += __shfl_xor_sync(0xffffu, t2, o);
        float var = t2 * (1.f / 64.f);
        float rs = rsqrtf(var + 1e-5f);

        float4 gv = *(const float4*)&g[tid * 4];
        float4 bb = *(const float4*)&b[tid * 4];
        float4 iv = *(const float4*)&idn[(size_t)n * 64 + tid * 4];
        float4 y;
        y.x = dx * rs * gv.x + bb.x + iv.x;
        y.y = dy * rs * gv.y + bb.y + iv.y;
        y.z = dz * rs * gv.z + bb.z + iv.z;
        y.w = dw * rs * gv.w + bb.w + iv.w;
        y.x = y.x > 0.f ? y.x : expm1f(y.x);
        y.y = y.y > 0.f ? y.y : expm1f(y.y);
        y.z = y.z > 0.f ? y.z : expm1f(y.z);
        y.w = y.w > 0.f ? y.w : expm1f(y.w);
        *(float4*)&out[(size_t)n * 64 + tid * 4] = y;
    }
}

// ---------------- launcher ----------------
extern "C" void kernel_launch(void* const* d_in, const int* in_sizes, int n_in,
                              void* d_out, int out_size) {
    const float* x        = (const float*)d_in[0];
    const void*  ei       = d_in[1];
    const float* W1       = (const float*)d_in[2];
    const float* att_src1 = (const float*)d_in[3];
    const float* att_dst1 = (const float*)d_in[4];
    const float* bias1    = (const float*)d_in[5];
    const float* g1       = (const float*)d_in[6];
    const float* b1       = (const float*)d_in[7];
    const float* W2       = (const float*)d_in[8];
    const float* att_src2 = (const float*)d_in[9];
    const float* att_dst2 = (const float*)d_in[10];
    const float* bias2    = (const float*)d_in[11];
    const float* g2       = (const float*)d_in[12];
    const float* b2       = (const float*)d_in[13];
    const float* Wres     = (const float*)d_in[14];
    const float* bres     = (const float*)d_in[15];
    float* out = (float*)d_out;

    float *p_h1, *p_h1a, *p_h2, *p_id, *p_asrc, *p_adst;
    cudaGetSymbolAddress((void**)&p_h1,   g_h1);
    cudaGetSymbolAddress((void**)&p_h1a,  g_h1a);
    cudaGetSymbolAddress((void**)&p_h2,   g_h2);
    cudaGetSymbolAddress((void**)&p_id,   g_id);
    cudaGetSymbolAddress((void**)&p_asrc, g_asrc);
    cudaGetSymbolAddress((void**)&p_adst, g_adst);

    dim3 blk(256);

    // CSR build
    detect_kernel<<<1, 256>>>((const unsigned int*)ei);
    zero_deg_kernel<<<NB, 256>>>();
    count_kernel<<<(ET + 255) / 256, 256>>>(ei);
    bsum_kernel<<<NB, 256>>>();
    bscan_kernel<<<1, 256>>>();
    rowscan_kernel<<<NB, 256>>>();
    fill_kernel<<<(ET + 255) / 256, 256>>>(ei);

    // residual projection: id = x @ Wres + bres  [N,64]
    {
        dim3 grid(1, (NN + 127) / 128);
        sgemm128<<<grid, blk>>>(x, Wres, bres, p_id, NN, 64, INF_);
    }
    // layer-1 projection: h1 = x @ W1  [N,256]
    {
        dim3 grid(HC1 / 128, (NN + 127) / 128);
        sgemmTT<<<grid, blk>>>(x, W1, p_h1, NN, HC1, INF_);
    }
    alpha_kernel<<<(NN * HH + 7) / 8, 256>>>(p_h1, att_src1, att_dst1, p_asrc, p_adst);
    agg1_kernel<<<NN, 256>>>(p_h1, p_asrc, p_adst, bias1, g1, b1, p_h1a);

    // layer-2 projection: h2 = h1a @ W2  [N,256]
    {
        dim3 grid(HC2 / 128, (NN + 127) / 128);
        sgemmTT<<<grid, blk>>>(p_h1a, W2, p_h2, NN, HC2, HC1);
    }
    alpha_kernel<<<(NN * HH + 7) / 8, 256>>>(p_h2, att_src2, att_dst2, p_asrc, p_adst);
    agg2_kernel<<<NN, 256>>>(p_h2, p_asrc, p_adst, bias2, g2, b2, p_id, out);
}

// round 5
// speedup vs baseline: 3.5247x; 1.3061x over previous
#include <cuda_runtime.h>
#include <cuda_bf16.h>
#include <math.h>

// Problem constants
#define NN 50000
#define EE 800000
#define ET 850000            // EE + NN self loops
#define HH 4
#define HC1 256
#define CC2 64
#define HC2 256
#define INF_ 128
#define NB 196               // ceil(NN/256)

// ---------------- scratch (device globals; no allocation) ----------------
__device__ __align__(16) float g_h1[(size_t)NN * HC1];
__device__ __align__(16) float g_h1a[(size_t)NN * HC1];
__device__ __align__(16) float g_h2[(size_t)NN * HC2];
__device__ __align__(16) float g_id[(size_t)NN * CC2];
__device__ __align__(16) float g_asrc[NN * HH];
__device__ __align__(16) float g_adst[NN * HH];
__device__ __align__(16) float g_w[(size_t)ET * HH];
__device__ __align__(16) float g_sinv[NN * HH];
__device__ int   g_deg[NN];
__device__ int   g_row[NN + 1];
__device__ int   g_cursor[NN];
__device__ int   g_csr_src[ET];
__device__ int   g_bsum[NB];
__device__ int   g_boff[NB];
__device__ int   g_is64;

// ---------------- edge index dtype detection ----------------
__global__ void detect_kernel(const unsigned int* __restrict__ words) {
    __shared__ int any;
    if (threadIdx.x == 0) any = 0;
    __syncthreads();
    for (int i = threadIdx.x; i < 4096; i += blockDim.x)
        if (words[2 * i + 1] != 0u) any = 1;
    __syncthreads();
    if (threadIdx.x == 0) g_is64 = any ? 0 : 1;
}

__device__ __forceinline__ void load_edge(const void* ei, int e, int& src, int& dst) {
    if (e < EE) {
        if (g_is64) {
            const long long* p = (const long long*)ei;
            src = (int)p[e];
            dst = (int)p[EE + e];
        } else {
            const int* p = (const int*)ei;
            src = p[e];
            dst = p[EE + e];
        }
    } else {
        src = dst = e - EE;
    }
}

// ---------------- CSR build ----------------
__global__ void zero_deg_kernel() {
    int i = blockIdx.x * blockDim.x + threadIdx.x;
    if (i < NN) g_deg[i] = 0;
}

__global__ void count_kernel(const void* __restrict__ ei) {
    int e = blockIdx.x * blockDim.x + threadIdx.x;
    if (e >= ET) return;
    int s, d;
    load_edge(ei, e, s, d);
    atomicAdd(&g_deg[d], 1);
}

__global__ __launch_bounds__(256) void bsum_kernel() {
    __shared__ int sh[256];
    int i = blockIdx.x * 256 + threadIdx.x;
    sh[threadIdx.x] = (i < NN) ? g_deg[i] : 0;
    __syncthreads();
    for (int o = 128; o; o >>= 1) {
        if (threadIdx.x < o) sh[threadIdx.x] += sh[threadIdx.x + o];
        __syncthreads();
    }
    if (threadIdx.x == 0) g_bsum[blockIdx.x] = sh[0];
}

__global__ __launch_bounds__(256) void bscan_kernel() {
    __shared__ int sh[256];
    int tid = threadIdx.x;
    int v = (tid < NB) ? g_bsum[tid] : 0;
    sh[tid] = v;
    __syncthreads();
    for (int o = 1; o < 256; o <<= 1) {
        int t = 0;
        if (tid >= o) t = sh[tid - o];
        __syncthreads();
        sh[tid] += t;
        __syncthreads();
    }
    if (tid < NB) g_boff[tid] = sh[tid] - v;   // exclusive
    if (tid == 0) g_row[NN] = ET;
}

__global__ __launch_bounds__(256) void rowscan_kernel() {
    __shared__ int sh[256];
    int tid = threadIdx.x;
    int i = blockIdx.x * 256 + tid;
    int v = (i < NN) ? g_deg[i] : 0;
    sh[tid] = v;
    __syncthreads();
    for (int o = 1; o < 256; o <<= 1) {
        int t = 0;
        if (tid >= o) t = sh[tid - o];
        __syncthreads();
        sh[tid] += t;
        __syncthreads();
    }
    if (i < NN) {
        int r = g_boff[blockIdx.x] + sh[tid] - v;
        g_row[i] = r;
        g_cursor[i] = r;
    }
}

__global__ void fill_kernel(const void* __restrict__ ei) {
    int e = blockIdx.x * blockDim.x + threadIdx.x;
    if (e >= ET) return;
    int s, d;
    load_edge(ei, e, s, d);
    int pos = atomicAdd(&g_cursor[d], 1);
    g_csr_src[pos] = s;
}

// ---------------- SGEMM 128x128x8, 8x8 micro-tile ----------------
__global__ __launch_bounds__(256) void sgemmTT(
    const float* __restrict__ A, const float* __restrict__ B,
    float* __restrict__ C, int M, int Nc, int K)
{
    __shared__ __align__(16) float As[8][132];
    __shared__ __align__(16) float Bs[8][128];
    const int bx = blockIdx.x * 128;
    const int by = blockIdx.y * 128;
    const int tx = threadIdx.x & 15;
    const int ty = threadIdx.x >> 4;
    const int t  = threadIdx.x;

    float acc[8][8] = {};

    for (int k0 = 0; k0 < K; k0 += 8) {
        {
            int m = t >> 1, c = (t & 1) * 4;
            int gm = by + m;
            float4 av = make_float4(0.f, 0.f, 0.f, 0.f);
            if (gm < M) av = *(const float4*)&A[(size_t)gm * K + k0 + c];
            As[c + 0][m] = av.x;
            As[c + 1][m] = av.y;
            As[c + 2][m] = av.z;
            As[c + 3][m] = av.w;
        }
        {
            int kk = t >> 5, n4 = t & 31;
            float4 bv = *(const float4*)&B[(size_t)(k0 + kk) * Nc + bx + n4 * 4];
            *(float4*)&Bs[kk][n4 * 4] = bv;
        }
        __syncthreads();
        #pragma unroll
        for (int kk = 0; kk < 8; kk++) {
            float4 a0 = *(const float4*)&As[kk][ty * 8];
            float4 a1 = *(const float4*)&As[kk][ty * 8 + 4];
            float4 b0 = *(const float4*)&Bs[kk][tx * 8];
            float4 b1 = *(const float4*)&Bs[kk][tx * 8 + 4];
            float a[8] = {a0.x, a0.y, a0.z, a0.w, a1.x, a1.y, a1.z, a1.w};
            float b[8] = {b0.x, b0.y, b0.z, b0.w, b1.x, b1.y, b1.z, b1.w};
            #pragma unroll
            for (int i = 0; i < 8; i++)
                #pragma unroll
                for (int j = 0; j < 8; j++)
                    acc[i][j] = fmaf(a[i], b[j], acc[i][j]);
        }
        __syncthreads();
    }

    #pragma unroll
    for (int i = 0; i < 8; i++) {
        int gm = by + ty * 8 + i;
        if (gm >= M) continue;
        float4 o0 = make_float4(acc[i][0], acc[i][1], acc[i][2], acc[i][3]);
        float4 o1 = make_float4(acc[i][4], acc[i][5], acc[i][6], acc[i][7]);
        *(float4*)&C[(size_t)gm * Nc + bx + tx * 8]     = o0;
        *(float4*)&C[(size_t)gm * Nc + bx + tx * 8 + 4] = o1;
    }
}

// ---------------- SGEMM 128x64 (residual, Nc=64) ----------------
__global__ __launch_bounds__(256) void sgemm128(
    const float* __restrict__ A, const float* __restrict__ B,
    const float* __restrict__ bias, float* __restrict__ C,
    int M, int Nc, int K)
{
    __shared__ __align__(16) float As[8][132];
    __shared__ __align__(16) float Bs[8][68];
    const int bx = blockIdx.x * 64;
    const int by = blockIdx.y * 128;
    const int tx = threadIdx.x & 15;
    const int ty = threadIdx.x >> 4;

    float acc[8][4] = {};

    for (int k0 = 0; k0 < K; k0 += 8) {
        #pragma unroll
        for (int i = 0; i < 4; i++) {
            int idx = threadIdx.x + i * 256;
            int m = idx >> 3, k = idx & 7;
            int gm = by + m;
            As[k][m] = (gm < M) ? A[(size_t)gm * K + k0 + k] : 0.f;
        }
        #pragma unroll
        for (int i = 0; i < 2; i++) {
            int idx = threadIdx.x + i * 256;
            int kk = idx >> 6, n = idx & 63;
            Bs[kk][n] = B[(size_t)(k0 + kk) * Nc + bx + n];
        }
        __syncthreads();
        #pragma unroll
        for (int kk = 0; kk < 8; kk++) {
            float4 a0 = *(const float4*)&As[kk][ty * 8];
            float4 a1 = *(const float4*)&As[kk][ty * 8 + 4];
            float4 b0 = *(const float4*)&Bs[kk][tx * 4];
            float a[8] = {a0.x, a0.y, a0.z, a0.w, a1.x, a1.y, a1.z, a1.w};
            float bb[4] = {b0.x, b0.y, b0.z, b0.w};
            #pragma unroll
            for (int i = 0; i < 8; i++)
                #pragma unroll
                for (int j = 0; j < 4; j++)
                    acc[i][j] = fmaf(a[i], bb[j], acc[i][j]);
        }
        __syncthreads();
    }

    float4 bv = make_float4(0.f, 0.f, 0.f, 0.f);
    if (bias) bv = *(const float4*)&bias[bx + tx * 4];
    #pragma unroll
    for (int i = 0; i < 8; i++) {
        int gm = by + ty * 8 + i;
        if (gm >= M) continue;
        float4 o;
        o.x = acc[i][0] + bv.x;
        o.y = acc[i][1] + bv.y;
        o.z = acc[i][2] + bv.z;
        o.w = acc[i][3] + bv.w;
        *(float4*)&C[(size_t)gm * Nc + bx + tx * 4] = o;
    }
}

// ---------------- per-node attention coefficients ----------------
__global__ __launch_bounds__(256) void alpha_kernel(
    const float* __restrict__ h, const float* __restrict__ att_s,
    const float* __restrict__ att_d, float* __restrict__ asrc,
    float* __restrict__ adst)
{
    int warpId = (blockIdx.x * blockDim.x + threadIdx.x) >> 5;
    int lane = threadIdx.x & 31;
    if (warpId >= NN * HH) return;
    int n = warpId >> 2, hh = warpId & 3;
    const float* hp = h + (size_t)n * 256 + hh * 64;
    float v0 = hp[lane], v1 = hp[lane + 32];
    float s1 = v0 * att_s[hh * 64 + lane] + v1 * att_s[hh * 64 + lane + 32];
    float s2 = v0 * att_d[hh * 64 + lane] + v1 * att_d[hh * 64 + lane + 32];
    #pragma unroll
    for (int o = 16; o; o >>= 1) {
        s1 += __shfl_xor_sync(0xffffffffu, s1, o);
        s2 += __shfl_xor_sync(0xffffffffu, s2, o);
    }
    if (lane == 0) {
        asrc[warpId] = s1;
        adst[warpId] = s2;
    }
}

// ---------------- edge weights + per-node inverse denominators ----------------
// one warp per dst node
__global__ __launch_bounds__(256) void weight_kernel(
    const float* __restrict__ asrc, const float* __restrict__ adst,
    float* __restrict__ w, float* __restrict__ sinv)
{
    int n = (blockIdx.x * blockDim.x + threadIdx.x) >> 5;
    int lane = threadIdx.x & 31;
    if (n >= NN) return;
    int r0 = g_row[n], deg = g_row[n + 1] - r0;
    float4 ad = *(const float4*)&adst[n * 4];
    float d0 = 0.f, d1 = 0.f, d2 = 0.f, d3 = 0.f;
    for (int j = lane; j < deg; j += 32) {
        int s = g_csr_src[r0 + j];
        float4 as = *(const float4*)&asrc[s * 4];
        float e0 = as.x + ad.x; e0 = e0 > 0.f ? e0 : 0.2f * e0;
        float e1 = as.y + ad.y; e1 = e1 > 0.f ? e1 : 0.2f * e1;
        float e2 = as.z + ad.z; e2 = e2 > 0.f ? e2 : 0.2f * e2;
        float e3 = as.w + ad.w; e3 = e3 > 0.f ? e3 : 0.2f * e3;
        float4 wv = make_float4(__expf(e0), __expf(e1), __expf(e2), __expf(e3));
        *(float4*)&w[(size_t)(r0 + j) * 4] = wv;
        d0 += wv.x; d1 += wv.y; d2 += wv.z; d3 += wv.w;
    }
    #pragma unroll
    for (int o = 16; o; o >>= 1) {
        d0 += __shfl_xor_sync(0xffffffffu, d0, o);
        d1 += __shfl_xor_sync(0xffffffffu, d1, o);
        d2 += __shfl_xor_sync(0xffffffffu, d2, o);
        d3 += __shfl_xor_sync(0xffffffffu, d3, o);
    }
    if (lane == 0) {
        float4 iv = make_float4(1.f / d0, 1.f / d1, 1.f / d2, 1.f / d3);
        *(float4*)&sinv[n * 4] = iv;
    }
}

// ---------------- gather core: 64-thread group per node, unroll 8 ----------------
__device__ __forceinline__ float4 gather_node(
    int n, int q, int h, const float* __restrict__ hfeat,
    const float* __restrict__ w, const float* __restrict__ sinv)
{
    int r0 = g_row[n], deg = g_row[n + 1] - r0;
    const float* fp = hfeat + q * 4;
    float4 acc = make_float4(0.f, 0.f, 0.f, 0.f);
    int j = 0;
    for (; j + 8 <= deg; j += 8) {
        int s[8]; float wv[8];
        #pragma unroll
        for (int u = 0; u < 8; u++) {
            s[u]  = g_csr_src[r0 + j + u];
            wv[u] = w[(size_t)(r0 + j + u) * 4 + h];
        }
        #pragma unroll
        for (int u = 0; u < 8; u++) {
            float4 f = *(const float4*)&fp[(size_t)s[u] * 256];
            acc.x = fmaf(wv[u], f.x, acc.x);
            acc.y = fmaf(wv[u], f.y, acc.y);
            acc.z = fmaf(wv[u], f.z, acc.z);
            acc.w = fmaf(wv[u], f.w, acc.w);
        }
    }
    for (; j < deg; j++) {
        int s = g_csr_src[r0 + j];
        float wv = w[(size_t)(r0 + j) * 4 + h];
        float4 f = *(const float4*)&fp[(size_t)s * 256];
        acc.x = fmaf(wv, f.x, acc.x);
        acc.y = fmaf(wv, f.y, acc.y);
        acc.z = fmaf(wv, f.z, acc.z);
        acc.w = fmaf(wv, f.w, acc.w);
    }
    float sc = sinv[n * 4 + h];
    acc.x *= sc; acc.y *= sc; acc.z *= sc; acc.w *= sc;
    return acc;
}

// ---------------- layer 1: gather + bias + LN(256) + ELU ----------------
__global__ __launch_bounds__(256) void agg1_kernel(
    const float* __restrict__ hfeat, const float* __restrict__ w,
    const float* __restrict__ sinv, const float* __restrict__ bias,
    const float* __restrict__ g, const float* __restrict__ b,
    float* __restrict__ out)
{
    __shared__ float red[4][2];
    __shared__ float red2[4][2];
    int tid = threadIdx.x;
    int grp = tid >> 6, q = tid & 63, h = q >> 4;
    int n = blockIdx.x * 4 + grp;

    float4 acc = gather_node(n, q, h, hfeat, w, sinv);
    float4 bv = *(const float4*)&bias[q * 4];
    float4 v;
    v.x = acc.x + bv.x; v.y = acc.y + bv.y;
    v.z = acc.z + bv.z; v.w = acc.w + bv.w;

    int lane = tid & 31;
    float t = v.x + v.y + v.z + v.w;
    #pragma unroll
    for (int o = 16; o; o >>= 1) t += __shfl_xor_sync(0xffffffffu, t, o);
    if (lane == 0) red[grp][(tid >> 5) & 1] = t;
    __syncthreads();
    float mu = (red[grp][0] + red[grp][1]) * (1.f / 256.f);
    float dx = v.x - mu, dy = v.y - mu, dz = v.z - mu, dw = v.w - mu;
    float t2 = dx * dx + dy * dy + dz * dz + dw * dw;
    #pragma unroll
    for (int o = 16; o; o >>= 1) t2 += __shfl_xor_sync(0xffffffffu, t2, o);
    if (lane == 0) red2[grp][(tid >> 5) & 1] = t2;
    __syncthreads();
    float var = (red2[grp][0] + red2[grp][1]) * (1.f / 256.f);
    float rs = rsqrtf(var + 1e-5f);

    float4 gv = *(const float4*)&g[q * 4];
    float4 bb = *(const float4*)&b[q * 4];
    float4 y;
    y.x = dx * rs * gv.x + bb.x;
    y.y = dy * rs * gv.y + bb.y;
    y.z = dz * rs * gv.z + bb.z;
    y.w = dw * rs * gv.w + bb.w;
    y.x = y.x > 0.f ? y.x : expm1f(y.x);
    y.y = y.y > 0.f ? y.y : expm1f(y.y);
    y.z = y.z > 0.f ? y.z : expm1f(y.z);
    y.w = y.w > 0.f ? y.w : expm1f(y.w);
    *(float4*)&out[(size_t)n * 256 + q * 4] = y;
}

// ---------- layer 2: gather + head-mean + bias + LN(64) + res + ELU ----------
__global__ __launch_bounds__(256) void agg2_kernel(
    const float* __restrict__ hfeat, const float* __restrict__ w,
    const float* __restrict__ sinv, const float* __restrict__ bias,
    const float* __restrict__ g, const float* __restrict__ b,
    const float* __restrict__ idn, float* __restrict__ out)
{
    __shared__ __align__(16) float4 sv[4][64];
    int tid = threadIdx.x;
    int grp = tid >> 6, q = tid & 63, h = q >> 4;
    int n = blockIdx.x * 4 + grp;

    float4 acc = gather_node(n, q, h, hfeat, w, sinv);
    sv[grp][q] = acc;
    __syncthreads();

    if (q < 16) {
        float4 v0 = sv[grp][q],      v1 = sv[grp][q + 16];
        float4 v2 = sv[grp][q + 32], v3 = sv[grp][q + 48];
        float4 bv = *(const float4*)&bias[q * 4];
        float4 m;
        m.x = 0.25f * (v0.x + v1.x + v2.x + v3.x) + bv.x;
        m.y = 0.25f * (v0.y + v1.y + v2.y + v3.y) + bv.y;
        m.z = 0.25f * (v0.z + v1.z + v2.z + v3.z) + bv.z;
        m.w = 0.25f * (v0.w + v1.w + v2.w + v3.w) + bv.w;

        float t = m.x + m.y + m.z + m.w;
        #pragma unroll
        for (int o = 1; o < 16; o <<= 1) t += __shfl_xor_sync(0xffffu, t, o);
        float mu = t * (1.f / 64.f);
        float dx = m.x - mu, dy = m.y - mu, dz = m.z - mu, dw = m.w - mu;
        float t2 = dx * dx + dy * dy + dz * dz + dw * dw;
        #pragma unroll
        for (int o = 1; o < 16; o <<= 1) t2 += __shfl_xor_sync(0xffffu, t2, o);
        float var = t2 * (1.f / 64.f);
        float rs = rsqrtf(var + 1e-5f);

        float4 gv = *(const float4*)&g[q * 4];
        float4 bb = *(const float4*)&b[q * 4];
        float4 iv = *(const float4*)&idn[(size_t)n * 64 + q * 4];
        float4 y;
        y.x = dx * rs * gv.x + bb.x + iv.x;
        y.y = dy * rs * gv.y + bb.y + iv.y;
        y.z = dz * rs * gv.z + bb.z + iv.z;
        y.w = dw * rs * gv.w + bb.w + iv.w;
        y.x = y.x > 0.f ? y.x : expm1f(y.x);
        y.y = y.y > 0.f ? y.y : expm1f(y.y);
        y.z = y.z > 0.f ? y.z : expm1f(y.z);
        y.w = y.w > 0.f ? y.w : expm1f(y.w);
        *(float4*)&out[(size_t)n * 64 + q * 4] = y;
    }
}

// ---------------- launcher ----------------
extern "C" void kernel_launch(void* const* d_in, const int* in_sizes, int n_in,
                              void* d_out, int out_size) {
    const float* x        = (const float*)d_in[0];
    const void*  ei       = d_in[1];
    const float* W1       = (const float*)d_in[2];
    const float* att_src1 = (const float*)d_in[3];
    const float* att_dst1 = (const float*)d_in[4];
    const float* bias1    = (const float*)d_in[5];
    const float* g1       = (const float*)d_in[6];
    const float* b1       = (const float*)d_in[7];
    const float* W2       = (const float*)d_in[8];
    const float* att_src2 = (const float*)d_in[9];
    const float* att_dst2 = (const float*)d_in[10];
    const float* bias2    = (const float*)d_in[11];
    const float* g2       = (const float*)d_in[12];
    const float* b2       = (const float*)d_in[13];
    const float* Wres     = (const float*)d_in[14];
    const float* bres     = (const float*)d_in[15];
    float* out = (float*)d_out;

    float *p_h1, *p_h1a, *p_h2, *p_id, *p_asrc, *p_adst, *p_w, *p_sinv;
    cudaGetSymbolAddress((void**)&p_h1,   g_h1);
    cudaGetSymbolAddress((void**)&p_h1a,  g_h1a);
    cudaGetSymbolAddress((void**)&p_h2,   g_h2);
    cudaGetSymbolAddress((void**)&p_id,   g_id);
    cudaGetSymbolAddress((void**)&p_asrc, g_asrc);
    cudaGetSymbolAddress((void**)&p_adst, g_adst);
    cudaGetSymbolAddress((void**)&p_w,    g_w);
    cudaGetSymbolAddress((void**)&p_sinv, g_sinv);

    dim3 blk(256);

    // #1..#3: start CSR build (independent of gemm)
    detect_kernel<<<1, 256>>>((const unsigned int*)ei);
    zero_deg_kernel<<<NB, 256>>>();
    count_kernel<<<(ET + 255) / 256, 256>>>(ei);
    // #4: layer-1 projection (placed here so ncu profiles it)
    {
        dim3 grid(HC1 / 128, (NN + 127) / 128);
        sgemmTT<<<grid, blk>>>(x, W1, p_h1, NN, HC1, INF_);
    }
    // rest of CSR build
    bsum_kernel<<<NB, 256>>>();
    bscan_kernel<<<1, 256>>>();
    rowscan_kernel<<<NB, 256>>>();
    fill_kernel<<<(ET + 255) / 256, 256>>>(ei);
    // residual projection
    {
        dim3 grid(1, (NN + 127) / 128);
        sgemm128<<<grid, blk>>>(x, Wres, bres, p_id, NN, 64, INF_);
    }

    alpha_kernel<<<(NN * HH + 7) / 8, 256>>>(p_h1, att_src1, att_dst1, p_asrc, p_adst);
    weight_kernel<<<(NN * 32 + 255) / 256, 256>>>(p_asrc, p_adst, p_w, p_sinv);
    agg1_kernel<<<NN / 4, 256>>>(p_h1, p_w, p_sinv, bias1, g1, b1, p_h1a);

    {
        dim3 grid(HC2 / 128, (NN + 127) / 128);
        sgemmTT<<<grid, blk>>>(p_h1a, W2, p_h2, NN, HC2, HC1);
    }
    alpha_kernel<<<(NN * HH + 7) / 8, 256>>>(p_h2, att_src2, att_dst2, p_asrc, p_adst);
    weight_kernel<<<(NN * 32 + 255) / 256, 256>>>(p_asrc, p_adst, p_w, p_sinv);
    agg2_kernel<<<NN / 4, 256>>>(p_h2, p_w, p_sinv, bias2, g2, b2, p_id, out);
}

// round 6
// speedup vs baseline: 5.2270x; 1.4829x over previous
#include <cuda_runtime.h>
#include <cuda_bf16.h>
#include <math.h>

// Problem constants
#define NN 50000
#define EE 800000
#define ET 850000            // EE + NN self loops
#define HH 4
#define HC1 256
#define CC2 64
#define HC2 256
#define INF_ 128
#define NB 196               // ceil(NN/256)

// ---------------- scratch (device globals; no allocation) ----------------
__device__ __align__(16) float g_h1[(size_t)NN * HC1];
__device__ __align__(16) float g_h1a[(size_t)NN * HC1];
__device__ __align__(16) float g_h2[(size_t)NN * HC2];
__device__ __align__(16) float g_id[(size_t)NN * CC2];
__device__ __align__(16) float g_asrc[NN * HH];
__device__ __align__(16) float g_adst[NN * HH];
__device__ __align__(16) float g_w[(size_t)ET * HH];
__device__ __align__(16) float g_sinv[NN * HH];
__device__ int   g_deg[NN];
__device__ int   g_row[NN + 1];
__device__ int   g_cursor[NN];
__device__ int   g_csr_src[ET];
__device__ int   g_bsum[NB];
__device__ int   g_boff[NB];
__device__ int   g_is64;

// ---------------- edge index dtype detection ----------------
__global__ void detect_kernel(const unsigned int* __restrict__ words) {
    __shared__ int any;
    if (threadIdx.x == 0) any = 0;
    __syncthreads();
    for (int i = threadIdx.x; i < 4096; i += blockDim.x)
        if (words[2 * i + 1] != 0u) any = 1;
    __syncthreads();
    if (threadIdx.x == 0) g_is64 = any ? 0 : 1;
}

__device__ __forceinline__ void load_edge(const void* ei, int e, int& src, int& dst) {
    if (e < EE) {
        if (g_is64) {
            const long long* p = (const long long*)ei;
            src = (int)p[e];
            dst = (int)p[EE + e];
        } else {
            const int* p = (const int*)ei;
            src = p[e];
            dst = p[EE + e];
        }
    } else {
        src = dst = e - EE;
    }
}

// ---------------- CSR build ----------------
__global__ void zero_deg_kernel() {
    int i = blockIdx.x * blockDim.x + threadIdx.x;
    if (i < NN) g_deg[i] = 0;
}

__global__ void count_kernel(const void* __restrict__ ei) {
    int e = blockIdx.x * blockDim.x + threadIdx.x;
    if (e >= ET) return;
    int s, d;
    load_edge(ei, e, s, d);
    atomicAdd(&g_deg[d], 1);
}

__global__ __launch_bounds__(256) void bsum_kernel() {
    __shared__ int sh[256];
    int i = blockIdx.x * 256 + threadIdx.x;
    sh[threadIdx.x] = (i < NN) ? g_deg[i] : 0;
    __syncthreads();
    for (int o = 128; o; o >>= 1) {
        if (threadIdx.x < o) sh[threadIdx.x] += sh[threadIdx.x + o];
        __syncthreads();
    }
    if (threadIdx.x == 0) g_bsum[blockIdx.x] = sh[0];
}

__global__ __launch_bounds__(256) void bscan_kernel() {
    __shared__ int sh[256];
    int tid = threadIdx.x;
    int v = (tid < NB) ? g_bsum[tid] : 0;
    sh[tid] = v;
    __syncthreads();
    for (int o = 1; o < 256; o <<= 1) {
        int t = 0;
        if (tid >= o) t = sh[tid - o];
        __syncthreads();
        sh[tid] += t;
        __syncthreads();
    }
    if (tid < NB) g_boff[tid] = sh[tid] - v;   // exclusive
    if (tid == 0) g_row[NN] = ET;
}

__global__ __launch_bounds__(256) void rowscan_kernel() {
    __shared__ int sh[256];
    int tid = threadIdx.x;
    int i = blockIdx.x * 256 + tid;
    int v = (i < NN) ? g_deg[i] : 0;
    sh[tid] = v;
    __syncthreads();
    for (int o = 1; o < 256; o <<= 1) {
        int t = 0;
        if (tid >= o) t = sh[tid - o];
        __syncthreads();
        sh[tid] += t;
        __syncthreads();
    }
    if (i < NN) {
        int r = g_boff[blockIdx.x] + sh[tid] - v;
        g_row[i] = r;
        g_cursor[i] = r;
    }
}

__global__ void fill_kernel(const void* __restrict__ ei) {
    int e = blockIdx.x * blockDim.x + threadIdx.x;
    if (e >= ET) return;
    int s, d;
    load_edge(ei, e, s, d);
    int pos = atomicAdd(&g_cursor[d], 1);
    g_csr_src[pos] = s;
}

// ---------------- tf32 helpers ----------------
__device__ __forceinline__ unsigned f2tf(float f) {
    unsigned r;
    asm("cvt.rna.tf32.f32 %0, %1;" : "=r"(r) : "f"(f));
    return r;
}

__device__ __forceinline__ void mma_tf32(
    float& c0, float& c1, float& c2, float& c3,
    unsigned a0, unsigned a1, unsigned a2, unsigned a3,
    unsigned b0, unsigned b1)
{
    asm volatile(
        "mma.sync.aligned.m16n8k8.row.col.f32.tf32.tf32.f32 "
        "{%0,%1,%2,%3}, {%4,%5,%6,%7}, {%8,%9}, {%0,%1,%2,%3};"
        : "+f"(c0), "+f"(c1), "+f"(c2), "+f"(c3)
        : "r"(a0), "r"(a1), "r"(a2), "r"(a3), "r"(b0), "r"(b1));
}

// ---------------- tf32 tensor-core GEMM: 128x128x16 tiles ----------------
// 256 threads = 8 warps (4 along M x 2 along N); warp tile 32x64.
// Smem stride 136 (== 8 mod 32) -> conflict-free fragment LDS.
__global__ __launch_bounds__(256, 2) void sgemm_tf32(
    const float* __restrict__ A, const float* __restrict__ B,
    float* __restrict__ C, int M, int Nc, int K)
{
    __shared__ unsigned As[2][16][136];
    __shared__ unsigned Bs[2][16][136];

    const int t    = threadIdx.x;
    const int lane = t & 31;
    const int wid  = t >> 5;
    const int wm   = (wid & 3) * 32;
    const int wn   = (wid >> 2) * 64;
    const int bx   = blockIdx.x * 128;
    const int by   = blockIdx.y * 128;
    const int tg   = lane & 3;     // threadID_in_group
    const int gp   = lane >> 2;    // groupID

    float c[2][8][4] = {};

    const int NIT = K >> 4;
    float4 aReg[2], bReg[2];

    // stage tile 0
    #pragma unroll
    for (int i = 0; i < 2; i++) {
        int idx = t + i * 256;
        int m = idx >> 2, cc = (idx & 3) * 4;
        int gm = by + m;
        aReg[i] = (gm < M) ? *(const float4*)&A[(size_t)gm * K + cc]
                           : make_float4(0.f, 0.f, 0.f, 0.f);
        int kk = idx >> 5, n4 = idx & 31;
        int col = bx + n4 * 4;
        bReg[i] = (col < Nc) ? *(const float4*)&B[(size_t)kk * Nc + col]
                             : make_float4(0.f, 0.f, 0.f, 0.f);
    }
    #pragma unroll
    for (int i = 0; i < 2; i++) {
        int idx = t + i * 256;
        int m = idx >> 2, cc = (idx & 3) * 4;
        As[0][cc + 0][m] = f2tf(aReg[i].x);
        As[0][cc + 1][m] = f2tf(aReg[i].y);
        As[0][cc + 2][m] = f2tf(aReg[i].z);
        As[0][cc + 3][m] = f2tf(aReg[i].w);
        int kk = idx >> 5, n4 = idx & 31;
        Bs[0][kk][n4 * 4 + 0] = f2tf(bReg[i].x);
        Bs[0][kk][n4 * 4 + 1] = f2tf(bReg[i].y);
        Bs[0][kk][n4 * 4 + 2] = f2tf(bReg[i].z);
        Bs[0][kk][n4 * 4 + 3] = f2tf(bReg[i].w);
    }

    int p = 0;
    for (int it = 0; it < NIT; it++) {
        __syncthreads();
        // prefetch next tile into regs
        if (it + 1 < NIT) {
            int k0 = (it + 1) * 16;
            #pragma unroll
            for (int i = 0; i < 2; i++) {
                int idx = t + i * 256;
                int m = idx >> 2, cc = (idx & 3) * 4;
                int gm = by + m;
                aReg[i] = (gm < M) ? *(const float4*)&A[(size_t)gm * K + k0 + cc]
                                   : make_float4(0.f, 0.f, 0.f, 0.f);
                int kk = idx >> 5, n4 = idx & 31;
                int col = bx + n4 * 4;
                bReg[i] = (col < Nc) ? *(const float4*)&B[(size_t)(k0 + kk) * Nc + col]
                                     : make_float4(0.f, 0.f, 0.f, 0.f);
            }
        }
        // compute on buffer p: two k8 steps
        #pragma unroll
        for (int k8i = 0; k8i < 2; k8i++) {
            int kb = k8i * 8;
            unsigned a[2][4];
            #pragma unroll
            for (int mt = 0; mt < 2; mt++) {
                int m = wm + mt * 16 + gp;
                a[mt][0] = As[p][kb + tg][m];
                a[mt][1] = As[p][kb + tg][m + 8];
                a[mt][2] = As[p][kb + tg + 4][m];
                a[mt][3] = As[p][kb + tg + 4][m + 8];
            }
            #pragma unroll
            for (int nt = 0; nt < 8; nt++) {
                int n = wn + nt * 8 + gp;
                unsigned b0 = Bs[p][kb + tg][n];
                unsigned b1 = Bs[p][kb + tg + 4][n];
                #pragma unroll
                for (int mt = 0; mt < 2; mt++)
                    mma_tf32(c[mt][nt][0], c[mt][nt][1], c[mt][nt][2], c[mt][nt][3],
                             a[mt][0], a[mt][1], a[mt][2], a[mt][3], b0, b1);
            }
        }
        // store staged regs to other buffer
        if (it + 1 < NIT) {
            int q = p ^ 1;
            #pragma unroll
            for (int i = 0; i < 2; i++) {
                int idx = t + i * 256;
                int m = idx >> 2, cc = (idx & 3) * 4;
                As[q][cc + 0][m] = f2tf(aReg[i].x);
                As[q][cc + 1][m] = f2tf(aReg[i].y);
                As[q][cc + 2][m] = f2tf(aReg[i].z);
                As[q][cc + 3][m] = f2tf(aReg[i].w);
                int kk = idx >> 5, n4 = idx & 31;
                Bs[q][kk][n4 * 4 + 0] = f2tf(bReg[i].x);
                Bs[q][kk][n4 * 4 + 1] = f2tf(bReg[i].y);
                Bs[q][kk][n4 * 4 + 2] = f2tf(bReg[i].z);
                Bs[q][kk][n4 * 4 + 3] = f2tf(bReg[i].w);
            }
        }
        p ^= 1;
    }

    // epilogue
    #pragma unroll
    for (int mt = 0; mt < 2; mt++) {
        int r0 = by + wm + mt * 16 + gp;
        #pragma unroll
        for (int nt = 0; nt < 8; nt++) {
            int col = bx + wn + nt * 8 + 2 * tg;
            if (col >= Nc) continue;
            if (r0 < M)
                *(float2*)&C[(size_t)r0 * Nc + col] = make_float2(c[mt][nt][0], c[mt][nt][1]);
            if (r0 + 8 < M)
                *(float2*)&C[(size_t)(r0 + 8) * Nc + col] = make_float2(c[mt][nt][2], c[mt][nt][3]);
        }
    }
}

// ---------------- SGEMM 128x64 fp32 (residual, Nc=64) ----------------
__global__ __launch_bounds__(256) void sgemm128(
    const float* __restrict__ A, const float* __restrict__ B,
    const float* __restrict__ bias, float* __restrict__ C,
    int M, int Nc, int K)
{
    __shared__ __align__(16) float As[8][132];
    __shared__ __align__(16) float Bs[8][68];
    const int bx = blockIdx.x * 64;
    const int by = blockIdx.y * 128;
    const int tx = threadIdx.x & 15;
    const int ty = threadIdx.x >> 4;

    float acc[8][4] = {};

    for (int k0 = 0; k0 < K; k0 += 8) {
        #pragma unroll
        for (int i = 0; i < 4; i++) {
            int idx = threadIdx.x + i * 256;
            int m = idx >> 3, k = idx & 7;
            int gm = by + m;
            As[k][m] = (gm < M) ? A[(size_t)gm * K + k0 + k] : 0.f;
        }
        #pragma unroll
        for (int i = 0; i < 2; i++) {
            int idx = threadIdx.x + i * 256;
            int kk = idx >> 6, n = idx & 63;
            Bs[kk][n] = B[(size_t)(k0 + kk) * Nc + bx + n];
        }
        __syncthreads();
        #pragma unroll
        for (int kk = 0; kk < 8; kk++) {
            float4 a0 = *(const float4*)&As[kk][ty * 8];
            float4 a1 = *(const float4*)&As[kk][ty * 8 + 4];
            float4 b0 = *(const float4*)&Bs[kk][tx * 4];
            float a[8] = {a0.x, a0.y, a0.z, a0.w, a1.x, a1.y, a1.z, a1.w};
            float bb[4] = {b0.x, b0.y, b0.z, b0.w};
            #pragma unroll
            for (int i = 0; i < 8; i++)
                #pragma unroll
                for (int j = 0; j < 4; j++)
                    acc[i][j] = fmaf(a[i], bb[j], acc[i][j]);
        }
        __syncthreads();
    }

    float4 bv = make_float4(0.f, 0.f, 0.f, 0.f);
    if (bias) bv = *(const float4*)&bias[bx + tx * 4];
    #pragma unroll
    for (int i = 0; i < 8; i++) {
        int gm = by + ty * 8 + i;
        if (gm >= M) continue;
        float4 o;
        o.x = acc[i][0] + bv.x;
        o.y = acc[i][1] + bv.y;
        o.z = acc[i][2] + bv.z;
        o.w = acc[i][3] + bv.w;
        *(float4*)&C[(size_t)gm * Nc + bx + tx * 4] = o;
    }
}

// ---------------- per-node attention coefficients ----------------
__global__ __launch_bounds__(256) void alpha_kernel(
    const float* __restrict__ h, const float* __restrict__ att_s,
    const float* __restrict__ att_d, float* __restrict__ asrc,
    float* __restrict__ adst)
{
    int warpId = (blockIdx.x * blockDim.x + threadIdx.x) >> 5;
    int lane = threadIdx.x & 31;
    if (warpId >= NN * HH) return;
    int n = warpId >> 2, hh = warpId & 3;
    const float* hp = h + (size_t)n * 256 + hh * 64;
    float v0 = hp[lane], v1 = hp[lane + 32];
    float s1 = v0 * att_s[hh * 64 + lane] + v1 * att_s[hh * 64 + lane + 32];
    float s2 = v0 * att_d[hh * 64 + lane] + v1 * att_d[hh * 64 + lane + 32];
    #pragma unroll
    for (int o = 16; o; o >>= 1) {
        s1 += __shfl_xor_sync(0xffffffffu, s1, o);
        s2 += __shfl_xor_sync(0xffffffffu, s2, o);
    }
    if (lane == 0) {
        asrc[warpId] = s1;
        adst[warpId] = s2;
    }
}

// ---------------- edge weights + per-node inverse denominators ----------------
__global__ __launch_bounds__(256) void weight_kernel(
    const float* __restrict__ asrc, const float* __restrict__ adst,
    float* __restrict__ w, float* __restrict__ sinv)
{
    int n = (blockIdx.x * blockDim.x + threadIdx.x) >> 5;
    int lane = threadIdx.x & 31;
    if (n >= NN) return;
    int r0 = g_row[n], deg = g_row[n + 1] - r0;
    float4 ad = *(const float4*)&adst[n * 4];
    float d0 = 0.f, d1 = 0.f, d2 = 0.f, d3 = 0.f;
    for (int j = lane; j < deg; j += 32) {
        int s = g_csr_src[r0 + j];
        float4 as = *(const float4*)&asrc[s * 4];
        float e0 = as.x + ad.x; e0 = e0 > 0.f ? e0 : 0.2f * e0;
        float e1 = as.y + ad.y; e1 = e1 > 0.f ? e1 : 0.2f * e1;
        float e2 = as.z + ad.z; e2 = e2 > 0.f ? e2 : 0.2f * e2;
        float e3 = as.w + ad.w; e3 = e3 > 0.f ? e3 : 0.2f * e3;
        float4 wv = make_float4(__expf(e0), __expf(e1), __expf(e2), __expf(e3));
        *(float4*)&w[(size_t)(r0 + j) * 4] = wv;
        d0 += wv.x; d1 += wv.y; d2 += wv.z; d3 += wv.w;
    }
    #pragma unroll
    for (int o = 16; o; o >>= 1) {
        d0 += __shfl_xor_sync(0xffffffffu, d0, o);
        d1 += __shfl_xor_sync(0xffffffffu, d1, o);
        d2 += __shfl_xor_sync(0xffffffffu, d2, o);
        d3 += __shfl_xor_sync(0xffffffffu, d3, o);
    }
    if (lane == 0) {
        float4 iv = make_float4(1.f / d0, 1.f / d1, 1.f / d2, 1.f / d3);
        *(float4*)&sinv[n * 4] = iv;
    }
}

// ---------------- gather core ----------------
__device__ __forceinline__ float4 gather_node(
    int n, int q, int h, const float* __restrict__ hfeat,
    const float* __restrict__ w, const float* __restrict__ sinv)
{
    int r0 = g_row[n], deg = g_row[n + 1] - r0;
    const float* fp = hfeat + q * 4;
    float4 acc = make_float4(0.f, 0.f, 0.f, 0.f);
    int j = 0;
    for (; j + 8 <= deg; j += 8) {
        int s[8]; float wv[8];
        #pragma unroll
        for (int u = 0; u < 8; u++) {
            s[u]  = g_csr_src[r0 + j + u];
            wv[u] = w[(size_t)(r0 + j + u) * 4 + h];
        }
        #pragma unroll
        for (int u = 0; u < 8; u++) {
            float4 f = *(const float4*)&fp[(size_t)s[u] * 256];
            acc.x = fmaf(wv[u], f.x, acc.x);
            acc.y = fmaf(wv[u], f.y, acc.y);
            acc.z = fmaf(wv[u], f.z, acc.z);
            acc.w = fmaf(wv[u], f.w, acc.w);
        }
    }
    for (; j < deg; j++) {
        int s = g_csr_src[r0 + j];
        float wv = w[(size_t)(r0 + j) * 4 + h];
        float4 f = *(const float4*)&fp[(size_t)s * 256];
        acc.x = fmaf(wv, f.x, acc.x);
        acc.y = fmaf(wv, f.y, acc.y);
        acc.z = fmaf(wv, f.z, acc.z);
        acc.w = fmaf(wv, f.w, acc.w);
    }
    float sc = sinv[n * 4 + h];
    acc.x *= sc; acc.y *= sc; acc.z *= sc; acc.w *= sc;
    return acc;
}

// ---------------- layer 1: gather + bias + LN(256) + ELU ----------------
__global__ __launch_bounds__(256) void agg1_kernel(
    const float* __restrict__ hfeat, const float* __restrict__ w,
    const float* __restrict__ sinv, const float* __restrict__ bias,
    const float* __restrict__ g, const float* __restrict__ b,
    float* __restrict__ out)
{
    __shared__ float red[4][2];
    __shared__ float red2[4][2];
    int tid = threadIdx.x;
    int grp = tid >> 6, q = tid & 63, h = q >> 4;
    int n = blockIdx.x * 4 + grp;

    float4 acc = gather_node(n, q, h, hfeat, w, sinv);
    float4 bv = *(const float4*)&bias[q * 4];
    float4 v;
    v.x = acc.x + bv.x; v.y = acc.y + bv.y;
    v.z = acc.z + bv.z; v.w = acc.w + bv.w;

    int lane = tid & 31;
    float t = v.x + v.y + v.z + v.w;
    #pragma unroll
    for (int o = 16; o; o >>= 1) t += __shfl_xor_sync(0xffffffffu, t, o);
    if (lane == 0) red[grp][(tid >> 5) & 1] = t;
    __syncthreads();
    float mu = (red[grp][0] + red[grp][1]) * (1.f / 256.f);
    float dx = v.x - mu, dy = v.y - mu, dz = v.z - mu, dw = v.w - mu;
    float t2 = dx * dx + dy * dy + dz * dz + dw * dw;
    #pragma unroll
    for (int o = 16; o; o >>= 1) t2 += __shfl_xor_sync(0xffffffffu, t2, o);
    if (lane == 0) red2[grp][(tid >> 5) & 1] = t2;
    __syncthreads();
    float var = (red2[grp][0] + red2[grp][1]) * (1.f / 256.f);
    float rs = rsqrtf(var + 1e-5f);

    float4 gv = *(const float4*)&g[q * 4];
    float4 bb = *(const float4*)&b[q * 4];
    float4 y;
    y.x = dx * rs * gv.x + bb.x;
    y.y = dy * rs * gv.y + bb.y;
    y.z = dz * rs * gv.z + bb.z;
    y.w = dw * rs * gv.w + bb.w;
    y.x = y.x > 0.f ? y.x : expm1f(y.x);
    y.y = y.y > 0.f ? y.y : expm1f(y.y);
    y.z = y.z > 0.f ? y.z : expm1f(y.z);
    y.w = y.w > 0.f ? y.w : expm1f(y.w);
    *(float4*)&out[(size_t)n * 256 + q * 4] = y;
}

// ---------- layer 2: gather + head-mean + bias + LN(64) + res + ELU ----------
__global__ __launch_bounds__(256) void agg2_kernel(
    const float* __restrict__ hfeat, const float* __restrict__ w,
    const float* __restrict__ sinv, const float* __restrict__ bias,
    const float* __restrict__ g, const float* __restrict__ b,
    const float* __restrict__ idn, float* __restrict__ out)
{
    __shared__ __align__(16) float4 sv[4][64];
    int tid = threadIdx.x;
    int grp = tid >> 6, q = tid & 63, h = q >> 4;
    int n = blockIdx.x * 4 + grp;

    float4 acc = gather_node(n, q, h, hfeat, w, sinv);
    sv[grp][q] = acc;
    __syncthreads();

    if (q < 16) {
        float4 v0 = sv[grp][q],      v1 = sv[grp][q + 16];
        float4 v2 = sv[grp][q + 32], v3 = sv[grp][q + 48];
        float4 bv = *(const float4*)&bias[q * 4];
        float4 m;
        m.x = 0.25f * (v0.x + v1.x + v2.x + v3.x) + bv.x;
        m.y = 0.25f * (v0.y + v1.y + v2.y + v3.y) + bv.y;
        m.z = 0.25f * (v0.z + v1.z + v2.z + v3.z) + bv.z;
        m.w = 0.25f * (v0.w + v1.w + v2.w + v3.w) + bv.w;

        float t = m.x + m.y + m.z + m.w;
        #pragma unroll
        for (int o = 1; o < 16; o <<= 1) t += __shfl_xor_sync(0xffffu, t, o);
        float mu = t * (1.f / 64.f);
        float dx = m.x - mu, dy = m.y - mu, dz = m.z - mu, dw = m.w - mu;
        float t2 = dx * dx + dy * dy + dz * dz + dw * dw;
        #pragma unroll
        for (int o = 1; o < 16; o <<= 1) t2 += __shfl_xor_sync(0xffffu, t2, o);
        float var = t2 * (1.f / 64.f);
        float rs = rsqrtf(var + 1e-5f);

        float4 gv = *(const float4*)&g[q * 4];
        float4 bb = *(const float4*)&b[q * 4];
        float4 iv = *(const float4*)&idn[(size_t)n * 64 + q * 4];
        float4 y;
        y.x = dx * rs * gv.x + bb.x + iv.x;
        y.y = dy * rs * gv.y + bb.y + iv.y;
        y.z = dz * rs * gv.z + bb.z + iv.z;
        y.w = dw * rs * gv.w + bb.w + iv.w;
        y.x = y.x > 0.f ? y.x : expm1f(y.x);
        y.y = y.y > 0.f ? y.y : expm1f(y.y);
        y.z = y.z > 0.f ? y.z : expm1f(y.z);
        y.w = y.w > 0.f ? y.w : expm1f(y.w);
        *(float4*)&out[(size_t)n * 64 + q * 4] = y;
    }
}

// ---------------- launcher ----------------
extern "C" void kernel_launch(void* const* d_in, const int* in_sizes, int n_in,
                              void* d_out, int out_size) {
    const float* x        = (const float*)d_in[0];
    const void*  ei       = d_in[1];
    const float* W1       = (const float*)d_in[2];
    const float* att_src1 = (const float*)d_in[3];
    const float* att_dst1 = (const float*)d_in[4];
    const float* bias1    = (const float*)d_in[5];
    const float* g1       = (const float*)d_in[6];
    const float* b1       = (const float*)d_in[7];
    const float* W2       = (const float*)d_in[8];
    const float* att_src2 = (const float*)d_in[9];
    const float* att_dst2 = (const float*)d_in[10];
    const float* bias2    = (const float*)d_in[11];
    const float* g2       = (const float*)d_in[12];
    const float* b2       = (const float*)d_in[13];
    const float* Wres     = (const float*)d_in[14];
    const float* bres     = (const float*)d_in[15];
    float* out = (float*)d_out;

    float *p_h1, *p_h1a, *p_h2, *p_id, *p_asrc, *p_adst, *p_w, *p_sinv;
    cudaGetSymbolAddress((void**)&p_h1,   g_h1);
    cudaGetSymbolAddress((void**)&p_h1a,  g_h1a);
    cudaGetSymbolAddress((void**)&p_h2,   g_h2);
    cudaGetSymbolAddress((void**)&p_id,   g_id);
    cudaGetSymbolAddress((void**)&p_asrc, g_asrc);
    cudaGetSymbolAddress((void**)&p_adst, g_adst);
    cudaGetSymbolAddress((void**)&p_w,    g_w);
    cudaGetSymbolAddress((void**)&p_sinv, g_sinv);

    dim3 blk(256);

    // #1..#3: start CSR build (independent of gemm)
    detect_kernel<<<1, 256>>>((const unsigned int*)ei);
    zero_deg_kernel<<<NB, 256>>>();
    count_kernel<<<(ET + 255) / 256, 256>>>(ei);
    // #4: layer-1 projection on tensor cores (profiling slot)
    {
        dim3 grid(HC1 / 128, (NN + 127) / 128);
        sgemm_tf32<<<grid, blk>>>(x, W1, p_h1, NN, HC1, INF_);
    }
    // rest of CSR build
    bsum_kernel<<<NB, 256>>>();
    bscan_kernel<<<1, 256>>>();
    rowscan_kernel<<<NB, 256>>>();
    fill_kernel<<<(ET + 255) / 256, 256>>>(ei);
    // residual projection (fp32 for accuracy: feeds output directly)
    {
        dim3 grid(1, (NN + 127) / 128);
        sgemm128<<<grid, blk>>>(x, Wres, bres, p_id, NN, 64, INF_);
    }

    alpha_kernel<<<(NN * HH + 7) / 8, 256>>>(p_h1, att_src1, att_dst1, p_asrc, p_adst);
    weight_kernel<<<(NN * 32 + 255) / 256, 256>>>(p_asrc, p_adst, p_w, p_sinv);
    agg1_kernel<<<NN / 4, 256>>>(p_h1, p_w, p_sinv, bias1, g1, b1, p_h1a);

    {
        dim3 grid(HC2 / 128, (NN + 127) / 128);
        sgemm_tf32<<<grid, blk>>>(p_h1a, W2, p_h2, NN, HC2, HC1);
    }
    alpha_kernel<<<(NN * HH + 7) / 8, 256>>>(p_h2, att_src2, att_dst2, p_asrc, p_adst);
    weight_kernel<<<(NN * 32 + 255) / 256, 256>>>(p_asrc, p_adst, p_w, p_sinv);
    agg2_kernel<<<NN / 4, 256>>>(p_h2, p_w, p_sinv, bias2, g2, b2, p_id, out);
}

// round 7
// speedup vs baseline: 5.7260x; 1.0955x over previous
#include <cuda_runtime.h>
#include <cuda_bf16.h>
#include <cuda_fp16.h>
#include <math.h>

// Problem constants
#define NN 50000
#define EE 800000
#define ET 850000            // EE + NN self loops
#define HH 4
#define HC1 256
#define CC2 64
#define HC2 256
#define INF_ 128
#define NB 196               // ceil(NN/256)

// ---------------- scratch (device globals; no allocation) ----------------
__device__ __align__(16) __half g_h1[(size_t)NN * HC1];
__device__ __align__(16) __half g_h1a[(size_t)NN * HC1];
__device__ __align__(16) __half g_h2[(size_t)NN * HC2];
__device__ __align__(16) float  g_id[(size_t)NN * CC2];
__device__ __align__(16) float  g_asrc[NN * HH];
__device__ __align__(16) float  g_adst[NN * HH];
__device__ __align__(16) float  g_w[(size_t)ET * HH];
__device__ __align__(16) float  g_sinv[NN * HH];
__device__ int   g_deg[NN];
__device__ int   g_row[NN + 1];
__device__ int   g_cursor[NN];
__device__ int   g_csr_src[ET];
__device__ int   g_bsum[NB];
__device__ int   g_boff[NB];
__device__ int   g_is64;

// ---------------- edge index dtype detection ----------------
__global__ void detect_kernel(const unsigned int* __restrict__ words) {
    __shared__ int any;
    if (threadIdx.x == 0) any = 0;
    __syncthreads();
    for (int i = threadIdx.x; i < 4096; i += blockDim.x)
        if (words[2 * i + 1] != 0u) any = 1;
    __syncthreads();
    if (threadIdx.x == 0) g_is64 = any ? 0 : 1;
}

__device__ __forceinline__ void load_edge(const void* ei, int e, int& src, int& dst) {
    if (e < EE) {
        if (g_is64) {
            const long long* p = (const long long*)ei;
            src = (int)p[e];
            dst = (int)p[EE + e];
        } else {
            const int* p = (const int*)ei;
            src = p[e];
            dst = p[EE + e];
        }
    } else {
        src = dst = e - EE;
    }
}

// ---------------- CSR build ----------------
__global__ void zero_deg_kernel() {
    int i = blockIdx.x * blockDim.x + threadIdx.x;
    if (i < NN) g_deg[i] = 0;
}

__global__ void count_kernel(const void* __restrict__ ei) {
    int e = blockIdx.x * blockDim.x + threadIdx.x;
    if (e >= ET) return;
    int s, d;
    load_edge(ei, e, s, d);
    atomicAdd(&g_deg[d], 1);
}

__global__ __launch_bounds__(256) void bsum_kernel() {
    __shared__ int sh[256];
    int i = blockIdx.x * 256 + threadIdx.x;
    sh[threadIdx.x] = (i < NN) ? g_deg[i] : 0;
    __syncthreads();
    for (int o = 128; o; o >>= 1) {
        if (threadIdx.x < o) sh[threadIdx.x] += sh[threadIdx.x + o];
        __syncthreads();
    }
    if (threadIdx.x == 0) g_bsum[blockIdx.x] = sh[0];
}

__global__ __launch_bounds__(256) void bscan_kernel() {
    __shared__ int sh[256];
    int tid = threadIdx.x;
    int v = (tid < NB) ? g_bsum[tid] : 0;
    sh[tid] = v;
    __syncthreads();
    for (int o = 1; o < 256; o <<= 1) {
        int t = 0;
        if (tid >= o) t = sh[tid - o];
        __syncthreads();
        sh[tid] += t;
        __syncthreads();
    }
    if (tid < NB) g_boff[tid] = sh[tid] - v;   // exclusive
    if (tid == 0) g_row[NN] = ET;
}

__global__ __launch_bounds__(256) void rowscan_kernel() {
    __shared__ int sh[256];
    int tid = threadIdx.x;
    int i = blockIdx.x * 256 + tid;
    int v = (i < NN) ? g_deg[i] : 0;
    sh[tid] = v;
    __syncthreads();
    for (int o = 1; o < 256; o <<= 1) {
        int t = 0;
        if (tid >= o) t = sh[tid - o];
        __syncthreads();
        sh[tid] += t;
        __syncthreads();
    }
    if (i < NN) {
        int r = g_boff[blockIdx.x] + sh[tid] - v;
        g_row[i] = r;
        g_cursor[i] = r;
    }
}

__global__ void fill_kernel(const void* __restrict__ ei) {
    int e = blockIdx.x * blockDim.x + threadIdx.x;
    if (e >= ET) return;
    int s, d;
    load_edge(ei, e, s, d);
    int pos = atomicAdd(&g_cursor[d], 1);
    g_csr_src[pos] = s;
}

// ---------------- tf32 helpers ----------------
__device__ __forceinline__ unsigned f2tf(float f) {
    unsigned r;
    asm("cvt.rna.tf32.f32 %0, %1;" : "=r"(r) : "f"(f));
    return r;
}

__device__ __forceinline__ void mma_tf32(
    float& c0, float& c1, float& c2, float& c3,
    unsigned a0, unsigned a1, unsigned a2, unsigned a3,
    unsigned b0, unsigned b1)
{
    asm volatile(
        "mma.sync.aligned.m16n8k8.row.col.f32.tf32.tf32.f32 "
        "{%0,%1,%2,%3}, {%4,%5,%6,%7}, {%8,%9}, {%0,%1,%2,%3};"
        : "+f"(c0), "+f"(c1), "+f"(c2), "+f"(c3)
        : "r"(a0), "r"(a1), "r"(a2), "r"(a3), "r"(b0), "r"(b1));
}

// ---------------- tf32 tensor-core GEMM: 128x128x16 tiles ----------------
// AHALF: A is __half (exact to tf32).  CHALF: C stored as __half.
// When !CHALF, optional bias added (fp32 out).
template<bool AHALF, bool CHALF>
__global__ __launch_bounds__(256, 2) void sgemm_tf32_t(
    const void* __restrict__ Av, const float* __restrict__ B,
    const float* __restrict__ bias, void* __restrict__ Cv,
    int M, int Nc, int K)
{
    __shared__ unsigned As[2][16][136];
    __shared__ unsigned Bs[2][16][136];

    const int t    = threadIdx.x;
    const int lane = t & 31;
    const int wid  = t >> 5;
    const int wm   = (wid & 3) * 32;
    const int wn   = (wid >> 2) * 64;
    const int bx   = blockIdx.x * 128;
    const int by   = blockIdx.y * 128;
    const int tg   = lane & 3;
    const int gp   = lane >> 2;

    float c[2][8][4] = {};
    const int NIT = K >> 4;

    float4 aReg[2];
    uint4  aRegH;
    float4 bReg[2];

    // ---- stage-load helpers (inlined manually) ----
    // load tile k0 into registers
    auto ldA = [&](int k0) {
        if constexpr (AHALF) {
            const __half* A = (const __half*)Av;
            int row = t >> 1, kh = (t & 1) * 8;
            int gm = by + row;
            aRegH = make_uint4(0u, 0u, 0u, 0u);
            if (gm < M) aRegH = *(const uint4*)&A[(size_t)gm * K + k0 + kh];
        } else {
            const float* A = (const float*)Av;
            #pragma unroll
            for (int i = 0; i < 2; i++) {
                int idx = t + i * 256;
                int m = idx >> 2, cc = (idx & 3) * 4;
                int gm = by + m;
                aReg[i] = (gm < M) ? *(const float4*)&A[(size_t)gm * K + k0 + cc]
                                   : make_float4(0.f, 0.f, 0.f, 0.f);
            }
        }
    };
    auto ldB = [&](int k0) {
        #pragma unroll
        for (int i = 0; i < 2; i++) {
            int idx = t + i * 256;
            int kk = idx >> 5, n4 = idx & 31;
            int col = bx + n4 * 4;
            bReg[i] = (col < Nc) ? *(const float4*)&B[(size_t)(k0 + kk) * Nc + col]
                                 : make_float4(0.f, 0.f, 0.f, 0.f);
        }
    };
    auto stA = [&](int buf) {
        if constexpr (AHALF) {
            int row = t >> 1, kh = (t & 1) * 8;
            const __half2* hp = (const __half2*)&aRegH;
            #pragma unroll
            for (int j = 0; j < 4; j++) {
                float2 f = __half22float2(hp[j]);
                As[buf][kh + 2 * j][row]     = f2tf(f.x);
                As[buf][kh + 2 * j + 1][row] = f2tf(f.y);
            }
        } else {
            #pragma unroll
            for (int i = 0; i < 2; i++) {
                int idx = t + i * 256;
                int m = idx >> 2, cc = (idx & 3) * 4;
                As[buf][cc + 0][m] = f2tf(aReg[i].x);
                As[buf][cc + 1][m] = f2tf(aReg[i].y);
                As[buf][cc + 2][m] = f2tf(aReg[i].z);
                As[buf][cc + 3][m] = f2tf(aReg[i].w);
            }
        }
    };
    auto stB = [&](int buf) {
        #pragma unroll
        for (int i = 0; i < 2; i++) {
            int idx = t + i * 256;
            int kk = idx >> 5, n4 = idx & 31;
            Bs[buf][kk][n4 * 4 + 0] = f2tf(bReg[i].x);
            Bs[buf][kk][n4 * 4 + 1] = f2tf(bReg[i].y);
            Bs[buf][kk][n4 * 4 + 2] = f2tf(bReg[i].z);
            Bs[buf][kk][n4 * 4 + 3] = f2tf(bReg[i].w);
        }
    };

    ldA(0); ldB(0);
    stA(0); stB(0);

    int p = 0;
    for (int it = 0; it < NIT; it++) {
        __syncthreads();
        if (it + 1 < NIT) { ldA((it + 1) * 16); ldB((it + 1) * 16); }
        #pragma unroll
        for (int k8i = 0; k8i < 2; k8i++) {
            int kb = k8i * 8;
            unsigned a[2][4];
            #pragma unroll
            for (int mt = 0; mt < 2; mt++) {
                int m = wm + mt * 16 + gp;
                a[mt][0] = As[p][kb + tg][m];
                a[mt][1] = As[p][kb + tg][m + 8];
                a[mt][2] = As[p][kb + tg + 4][m];
                a[mt][3] = As[p][kb + tg + 4][m + 8];
            }
            #pragma unroll
            for (int nt = 0; nt < 8; nt++) {
                int n = wn + nt * 8 + gp;
                unsigned b0 = Bs[p][kb + tg][n];
                unsigned b1 = Bs[p][kb + tg + 4][n];
                #pragma unroll
                for (int mt = 0; mt < 2; mt++)
                    mma_tf32(c[mt][nt][0], c[mt][nt][1], c[mt][nt][2], c[mt][nt][3],
                             a[mt][0], a[mt][1], a[mt][2], a[mt][3], b0, b1);
            }
        }
        if (it + 1 < NIT) { int q = p ^ 1; stA(q); stB(q); }
        p ^= 1;
    }

    // epilogue
    #pragma unroll
    for (int mt = 0; mt < 2; mt++) {
        int r0 = by + wm + mt * 16 + gp;
        #pragma unroll
        for (int nt = 0; nt < 8; nt++) {
            int col = bx + wn + nt * 8 + 2 * tg;
            if (col >= Nc) continue;
            if constexpr (CHALF) {
                __half* C = (__half*)Cv;
                if (r0 < M) {
                    __half2 h = __floats2half2_rn(c[mt][nt][0], c[mt][nt][1]);
                    *(__half2*)&C[(size_t)r0 * Nc + col] = h;
                }
                if (r0 + 8 < M) {
                    __half2 h = __floats2half2_rn(c[mt][nt][2], c[mt][nt][3]);
                    *(__half2*)&C[(size_t)(r0 + 8) * Nc + col] = h;
                }
            } else {
                float* C = (float*)Cv;
                float b0 = bias ? bias[col] : 0.f;
                float b1 = bias ? bias[col + 1] : 0.f;
                if (r0 < M)
                    *(float2*)&C[(size_t)r0 * Nc + col] =
                        make_float2(c[mt][nt][0] + b0, c[mt][nt][1] + b1);
                if (r0 + 8 < M)
                    *(float2*)&C[(size_t)(r0 + 8) * Nc + col] =
                        make_float2(c[mt][nt][2] + b0, c[mt][nt][3] + b1);
            }
        }
    }
}

// ---------------- per-node attention coefficients (fp16 features) ----------------
__global__ __launch_bounds__(256) void alpha_kernel(
    const __half* __restrict__ h, const float* __restrict__ att_s,
    const float* __restrict__ att_d, float* __restrict__ asrc,
    float* __restrict__ adst)
{
    int warpId = (blockIdx.x * blockDim.x + threadIdx.x) >> 5;
    int lane = threadIdx.x & 31;
    if (warpId >= NN * HH) return;
    int n = warpId >> 2, hh = warpId & 3;
    const __half* hp = h + (size_t)n * 256 + hh * 64;
    __half2 hv = *(const __half2*)&hp[2 * lane];
    float2 f = __half22float2(hv);
    float a0 = att_s[hh * 64 + 2 * lane], a1 = att_s[hh * 64 + 2 * lane + 1];
    float d0 = att_d[hh * 64 + 2 * lane], d1 = att_d[hh * 64 + 2 * lane + 1];
    float s1 = f.x * a0 + f.y * a1;
    float s2 = f.x * d0 + f.y * d1;
    #pragma unroll
    for (int o = 16; o; o >>= 1) {
        s1 += __shfl_xor_sync(0xffffffffu, s1, o);
        s2 += __shfl_xor_sync(0xffffffffu, s2, o);
    }
    if (lane == 0) {
        asrc[warpId] = s1;
        adst[warpId] = s2;
    }
}

// ---------------- edge weights + per-node inverse denominators ----------------
__global__ __launch_bounds__(256) void weight_kernel(
    const float* __restrict__ asrc, const float* __restrict__ adst,
    float* __restrict__ w, float* __restrict__ sinv)
{
    int n = (blockIdx.x * blockDim.x + threadIdx.x) >> 5;
    int lane = threadIdx.x & 31;
    if (n >= NN) return;
    int r0 = g_row[n], deg = g_row[n + 1] - r0;
    float4 ad = *(const float4*)&adst[n * 4];
    float d0 = 0.f, d1 = 0.f, d2 = 0.f, d3 = 0.f;
    for (int j = lane; j < deg; j += 32) {
        int s = g_csr_src[r0 + j];
        float4 as = *(const float4*)&asrc[s * 4];
        float e0 = as.x + ad.x; e0 = e0 > 0.f ? e0 : 0.2f * e0;
        float e1 = as.y + ad.y; e1 = e1 > 0.f ? e1 : 0.2f * e1;
        float e2 = as.z + ad.z; e2 = e2 > 0.f ? e2 : 0.2f * e2;
        float e3 = as.w + ad.w; e3 = e3 > 0.f ? e3 : 0.2f * e3;
        float4 wv = make_float4(__expf(e0), __expf(e1), __expf(e2), __expf(e3));
        *(float4*)&w[(size_t)(r0 + j) * 4] = wv;
        d0 += wv.x; d1 += wv.y; d2 += wv.z; d3 += wv.w;
    }
    #pragma unroll
    for (int o = 16; o; o >>= 1) {
        d0 += __shfl_xor_sync(0xffffffffu, d0, o);
        d1 += __shfl_xor_sync(0xffffffffu, d1, o);
        d2 += __shfl_xor_sync(0xffffffffu, d2, o);
        d3 += __shfl_xor_sync(0xffffffffu, d3, o);
    }
    if (lane == 0) {
        float4 iv = make_float4(1.f / d0, 1.f / d1, 1.f / d2, 1.f / d3);
        *(float4*)&sinv[n * 4] = iv;
    }
}

// ---------------- gather core (fp16 features, 8B/thread/row) ----------------
__device__ __forceinline__ float4 gather_node(
    int n, int q, int h, const __half* __restrict__ hfeat,
    const float* __restrict__ w, const float* __restrict__ sinv)
{
    int r0 = g_row[n], deg = g_row[n + 1] - r0;
    const __half* fp = hfeat + q * 4;
    float4 acc = make_float4(0.f, 0.f, 0.f, 0.f);
    int j = 0;
    for (; j + 8 <= deg; j += 8) {
        int s[8]; float wv[8];
        #pragma unroll
        for (int u = 0; u < 8; u++) {
            s[u]  = g_csr_src[r0 + j + u];
            wv[u] = w[(size_t)(r0 + j + u) * 4 + h];
        }
        #pragma unroll
        for (int u = 0; u < 8; u++) {
            uint2 raw = *(const uint2*)&fp[(size_t)s[u] * 256];
            float2 f0 = __half22float2(*(__half2*)&raw.x);
            float2 f1 = __half22float2(*(__half2*)&raw.y);
            acc.x = fmaf(wv[u], f0.x, acc.x);
            acc.y = fmaf(wv[u], f0.y, acc.y);
            acc.z = fmaf(wv[u], f1.x, acc.z);
            acc.w = fmaf(wv[u], f1.y, acc.w);
        }
    }
    for (; j < deg; j++) {
        int s = g_csr_src[r0 + j];
        float wv = w[(size_t)(r0 + j) * 4 + h];
        uint2 raw = *(const uint2*)&fp[(size_t)s * 256];
        float2 f0 = __half22float2(*(__half2*)&raw.x);
        float2 f1 = __half22float2(*(__half2*)&raw.y);
        acc.x = fmaf(wv, f0.x, acc.x);
        acc.y = fmaf(wv, f0.y, acc.y);
        acc.z = fmaf(wv, f1.x, acc.z);
        acc.w = fmaf(wv, f1.y, acc.w);
    }
    float sc = sinv[n * 4 + h];
    acc.x *= sc; acc.y *= sc; acc.z *= sc; acc.w *= sc;
    return acc;
}

// ---------------- layer 1: gather + bias + LN(256) + ELU -> fp16 ----------------
__global__ __launch_bounds__(256) void agg1_kernel(
    const __half* __restrict__ hfeat, const float* __restrict__ w,
    const float* __restrict__ sinv, const float* __restrict__ bias,
    const float* __restrict__ g, const float* __restrict__ b,
    __half* __restrict__ out)
{
    __shared__ float red[4][2];
    __shared__ float red2[4][2];
    int tid = threadIdx.x;
    int grp = tid >> 6, q = tid & 63, h = q >> 4;
    int n = blockIdx.x * 4 + grp;

    float4 acc = gather_node(n, q, h, hfeat, w, sinv);
    float4 bv = *(const float4*)&bias[q * 4];
    float4 v;
    v.x = acc.x + bv.x; v.y = acc.y + bv.y;
    v.z = acc.z + bv.z; v.w = acc.w + bv.w;

    int lane = tid & 31;
    float t = v.x + v.y + v.z + v.w;
    #pragma unroll
    for (int o = 16; o; o >>= 1) t += __shfl_xor_sync(0xffffffffu, t, o);
    if (lane == 0) red[grp][(tid >> 5) & 1] = t;
    __syncthreads();
    float mu = (red[grp][0] + red[grp][1]) * (1.f / 256.f);
    float dx = v.x - mu, dy = v.y - mu, dz = v.z - mu, dw = v.w - mu;
    float t2 = dx * dx + dy * dy + dz * dz + dw * dw;
    #pragma unroll
    for (int o = 16; o; o >>= 1) t2 += __shfl_xor_sync(0xffffffffu, t2, o);
    if (lane == 0) red2[grp][(tid >> 5) & 1] = t2;
    __syncthreads();
    float var = (red2[grp][0] + red2[grp][1]) * (1.f / 256.f);
    float rs = rsqrtf(var + 1e-5f);

    float4 gv = *(const float4*)&g[q * 4];
    float4 bb = *(const float4*)&b[q * 4];
    float4 y;
    y.x = dx * rs * gv.x + bb.x;
    y.y = dy * rs * gv.y + bb.y;
    y.z = dz * rs * gv.z + bb.z;
    y.w = dw * rs * gv.w + bb.w;
    y.x = y.x > 0.f ? y.x : expm1f(y.x);
    y.y = y.y > 0.f ? y.y : expm1f(y.y);
    y.z = y.z > 0.f ? y.z : expm1f(y.z);
    y.w = y.w > 0.f ? y.w : expm1f(y.w);

    __half2 p0 = __floats2half2_rn(y.x, y.y);
    __half2 p1 = __floats2half2_rn(y.z, y.w);
    uint2 u;
    u.x = *(unsigned*)&p0;
    u.y = *(unsigned*)&p1;
    *(uint2*)&out[(size_t)n * 256 + q * 4] = u;
}

// ---------- layer 2: gather + head-mean + bias + LN(64) + res + ELU ----------
__global__ __launch_bounds__(256) void agg2_kernel(
    const __half* __restrict__ hfeat, const float* __restrict__ w,
    const float* __restrict__ sinv, const float* __restrict__ bias,
    const float* __restrict__ g, const float* __restrict__ b,
    const float* __restrict__ idn, float* __restrict__ out)
{
    __shared__ __align__(16) float4 sv[4][64];
    int tid = threadIdx.x;
    int grp = tid >> 6, q = tid & 63, h = q >> 4;
    int n = blockIdx.x * 4 + grp;

    float4 acc = gather_node(n, q, h, hfeat, w, sinv);
    sv[grp][q] = acc;
    __syncthreads();

    if (q < 16) {
        float4 v0 = sv[grp][q],      v1 = sv[grp][q + 16];
        float4 v2 = sv[grp][q + 32], v3 = sv[grp][q + 48];
        float4 bv = *(const float4*)&bias[q * 4];
        float4 m;
        m.x = 0.25f * (v0.x + v1.x + v2.x + v3.x) + bv.x;
        m.y = 0.25f * (v0.y + v1.y + v2.y + v3.y) + bv.y;
        m.z = 0.25f * (v0.z + v1.z + v2.z + v3.z) + bv.z;
        m.w = 0.25f * (v0.w + v1.w + v2.w + v3.w) + bv.w;

        float t = m.x + m.y + m.z + m.w;
        #pragma unroll
        for (int o = 1; o < 16; o <<= 1) t += __shfl_xor_sync(0xffffu, t, o);
        float mu = t * (1.f / 64.f);
        float dx = m.x - mu, dy = m.y - mu, dz = m.z - mu, dw = m.w - mu;
        float t2 = dx * dx + dy * dy + dz * dz + dw * dw;
        #pragma unroll
        for (int o = 1; o < 16; o <<= 1) t2 += __shfl_xor_sync(0xffffu, t2, o);
        float var = t2 * (1.f / 64.f);
        float rs = rsqrtf(var + 1e-5f);

        float4 gv = *(const float4*)&g[q * 4];
        float4 bb = *(const float4*)&b[q * 4];
        float4 iv = *(const float4*)&idn[(size_t)n * 64 + q * 4];
        float4 y;
        y.x = dx * rs * gv.x + bb.x + iv.x;
        y.y = dy * rs * gv.y + bb.y + iv.y;
        y.z = dz * rs * gv.z + bb.z + iv.z;
        y.w = dw * rs * gv.w + bb.w + iv.w;
        y.x = y.x > 0.f ? y.x : expm1f(y.x);
        y.y = y.y > 0.f ? y.y : expm1f(y.y);
        y.z = y.z > 0.f ? y.z : expm1f(y.z);
        y.w = y.w > 0.f ? y.w : expm1f(y.w);
        *(float4*)&out[(size_t)n * 64 + q * 4] = y;
    }
}

// ---------------- launcher ----------------
extern "C" void kernel_launch(void* const* d_in, const int* in_sizes, int n_in,
                              void* d_out, int out_size) {
    const float* x        = (const float*)d_in[0];
    const void*  ei       = d_in[1];
    const float* W1       = (const float*)d_in[2];
    const float* att_src1 = (const float*)d_in[3];
    const float* att_dst1 = (const float*)d_in[4];
    const float* bias1    = (const float*)d_in[5];
    const float* g1       = (const float*)d_in[6];
    const float* b1       = (const float*)d_in[7];
    const float* W2       = (const float*)d_in[8];
    const float* att_src2 = (const float*)d_in[9];
    const float* att_dst2 = (const float*)d_in[10];
    const float* bias2    = (const float*)d_in[11];
    const float* g2       = (const float*)d_in[12];
    const float* b2       = (const float*)d_in[13];
    const float* Wres     = (const float*)d_in[14];
    const float* bres     = (const float*)d_in[15];
    float* out = (float*)d_out;

    __half *p_h1, *p_h1a, *p_h2;
    float *p_id, *p_asrc, *p_adst, *p_w, *p_sinv;
    cudaGetSymbolAddress((void**)&p_h1,   g_h1);
    cudaGetSymbolAddress((void**)&p_h1a,  g_h1a);
    cudaGetSymbolAddress((void**)&p_h2,   g_h2);
    cudaGetSymbolAddress((void**)&p_id,   g_id);
    cudaGetSymbolAddress((void**)&p_asrc, g_asrc);
    cudaGetSymbolAddress((void**)&p_adst, g_adst);
    cudaGetSymbolAddress((void**)&p_w,    g_w);
    cudaGetSymbolAddress((void**)&p_sinv, g_sinv);

    dim3 blk(256);

    // CSR build start
    detect_kernel<<<1, 256>>>((const unsigned int*)ei);
    zero_deg_kernel<<<NB, 256>>>();
    count_kernel<<<(ET + 255) / 256, 256>>>(ei);
    // #4: layer-1 projection (profiling slot): x(fp32) @ W1 -> h1 (fp16)
    {
        dim3 grid(HC1 / 128, (NN + 127) / 128);
        sgemm_tf32_t<false, true><<<grid, blk>>>(x, W1, nullptr, p_h1, NN, HC1, INF_);
    }
    // rest of CSR build
    bsum_kernel<<<NB, 256>>>();
    bscan_kernel<<<1, 256>>>();
    rowscan_kernel<<<NB, 256>>>();
    fill_kernel<<<(ET + 255) / 256, 256>>>(ei);
    // residual: x(fp32) @ Wres + bres -> id (fp32)
    {
        dim3 grid(1, (NN + 127) / 128);
        sgemm_tf32_t<false, false><<<grid, blk>>>(x, Wres, bres, p_id, NN, 64, INF_);
    }

    alpha_kernel<<<(NN * HH + 7) / 8, 256>>>(p_h1, att_src1, att_dst1, p_asrc, p_adst);
    weight_kernel<<<(NN * 32 + 255) / 256, 256>>>(p_asrc, p_adst, p_w, p_sinv);
    agg1_kernel<<<NN / 4, 256>>>(p_h1, p_w, p_sinv, bias1, g1, b1, p_h1a);

    // layer-2 projection: h1a(fp16) @ W2 -> h2 (fp16)
    {
        dim3 grid(HC2 / 128, (NN + 127) / 128);
        sgemm_tf32_t<true, true><<<grid, blk>>>(p_h1a, W2, nullptr, p_h2, NN, HC2, HC1);
    }
    alpha_kernel<<<(NN * HH + 7) / 8, 256>>>(p_h2, att_src2, att_dst2, p_asrc, p_adst);
    weight_kernel<<<(NN * 32 + 255) / 256, 256>>>(p_asrc, p_adst, p_w, p_sinv);
    agg2_kernel<<<NN / 4, 256>>>(p_h2, p_w, p_sinv, bias2, g2, b2, p_id, out);
}

// round 8
// speedup vs baseline: 6.4558x; 1.1275x over previous
#include <cuda_runtime.h>
#include <cuda_bf16.h>
#include <cuda_fp16.h>
#include <math.h>

// Problem constants
#define NN 50000
#define EE 800000
#define ET 850000            // EE + NN self loops
#define HH 4
#define HC1 256
#define CC2 64
#define HC2 256
#define INF_ 128
#define NB 196               // ceil(NN/256)

// ---------------- scratch (device globals; no allocation) ----------------
__device__ __align__(16) __half g_h1[(size_t)NN * HC1];
__device__ __align__(16) __half g_h1a[(size_t)NN * HC1];
__device__ __align__(16) __half g_h2[(size_t)NN * HC2];
__device__ __align__(16) float  g_id[(size_t)NN * CC2];
__device__ __align__(16) float  g_asrc[NN * HH];
__device__ __align__(16) float  g_adst[NN * HH];
__device__ __align__(16) float  g_w[(size_t)ET * HH];
__device__ __align__(16) float  g_sinv[NN * HH];
__device__ int   g_deg[NN];
__device__ int   g_row[NN + 1];
__device__ int   g_cursor[NN];
__device__ int   g_csr_src[ET];
__device__ int   g_bsum[NB];
__device__ int   g_boff[NB];
__device__ int   g_is64;

// ---------------- edge index dtype detection ----------------
__global__ void detect_kernel(const unsigned int* __restrict__ words) {
    __shared__ int any;
    if (threadIdx.x == 0) any = 0;
    __syncthreads();
    for (int i = threadIdx.x; i < 4096; i += blockDim.x)
        if (words[2 * i + 1] != 0u) any = 1;
    __syncthreads();
    if (threadIdx.x == 0) g_is64 = any ? 0 : 1;
}

__device__ __forceinline__ void load_edge(const void* ei, int e, int& src, int& dst) {
    if (e < EE) {
        if (g_is64) {
            const long long* p = (const long long*)ei;
            src = (int)p[e];
            dst = (int)p[EE + e];
        } else {
            const int* p = (const int*)ei;
            src = p[e];
            dst = p[EE + e];
        }
    } else {
        src = dst = e - EE;
    }
}

// ---------------- CSR build ----------------
__global__ void zero_deg_kernel() {
    int i = blockIdx.x * blockDim.x + threadIdx.x;
    if (i < NN) g_deg[i] = 0;
}

__global__ void count_kernel(const void* __restrict__ ei) {
    int e = blockIdx.x * blockDim.x + threadIdx.x;
    if (e >= ET) return;
    int s, d;
    load_edge(ei, e, s, d);
    atomicAdd(&g_deg[d], 1);
}

__global__ __launch_bounds__(256) void bsum_kernel() {
    __shared__ int sh[256];
    int i = blockIdx.x * 256 + threadIdx.x;
    sh[threadIdx.x] = (i < NN) ? g_deg[i] : 0;
    __syncthreads();
    for (int o = 128; o; o >>= 1) {
        if (threadIdx.x < o) sh[threadIdx.x] += sh[threadIdx.x + o];
        __syncthreads();
    }
    if (threadIdx.x == 0) g_bsum[blockIdx.x] = sh[0];
}

__global__ __launch_bounds__(256) void bscan_kernel() {
    __shared__ int sh[256];
    int tid = threadIdx.x;
    int v = (tid < NB) ? g_bsum[tid] : 0;
    sh[tid] = v;
    __syncthreads();
    for (int o = 1; o < 256; o <<= 1) {
        int t = 0;
        if (tid >= o) t = sh[tid - o];
        __syncthreads();
        sh[tid] += t;
        __syncthreads();
    }
    if (tid < NB) g_boff[tid] = sh[tid] - v;   // exclusive
    if (tid == 0) g_row[NN] = ET;
}

__global__ __launch_bounds__(256) void rowscan_kernel() {
    __shared__ int sh[256];
    int tid = threadIdx.x;
    int i = blockIdx.x * 256 + tid;
    int v = (i < NN) ? g_deg[i] : 0;
    sh[tid] = v;
    __syncthreads();
    for (int o = 1; o < 256; o <<= 1) {
        int t = 0;
        if (tid >= o) t = sh[tid - o];
        __syncthreads();
        sh[tid] += t;
        __syncthreads();
    }
    if (i < NN) {
        int r = g_boff[blockIdx.x] + sh[tid] - v;
        g_row[i] = r;
        g_cursor[i] = r;
    }
}

__global__ void fill_kernel(const void* __restrict__ ei) {
    int e = blockIdx.x * blockDim.x + threadIdx.x;
    if (e >= ET) return;
    int s, d;
    load_edge(ei, e, s, d);
    int pos = atomicAdd(&g_cursor[d], 1);
    g_csr_src[pos] = s;
}

// ---------------- tf32 helpers ----------------
__device__ __forceinline__ unsigned f2tf(float f) {
    unsigned r;
    asm("cvt.rna.tf32.f32 %0, %1;" : "=r"(r) : "f"(f));
    return r;
}

__device__ __forceinline__ void mma_tf32(
    float& c0, float& c1, float& c2, float& c3,
    unsigned a0, unsigned a1, unsigned a2, unsigned a3,
    unsigned b0, unsigned b1)
{
    asm volatile(
        "mma.sync.aligned.m16n8k8.row.col.f32.tf32.tf32.f32 "
        "{%0,%1,%2,%3}, {%4,%5,%6,%7}, {%8,%9}, {%0,%1,%2,%3};"
        : "+f"(c0), "+f"(c1), "+f"(c2), "+f"(c3)
        : "r"(a0), "r"(a1), "r"(a2), "r"(a3), "r"(b0), "r"(b1));
}

// ---------------- tf32 tensor-core GEMM: 128x128x16 tiles ----------------
template<bool AHALF, bool CHALF>
__global__ __launch_bounds__(256, 2) void sgemm_tf32_t(
    const void* __restrict__ Av, const float* __restrict__ B,
    const float* __restrict__ bias, void* __restrict__ Cv,
    int M, int Nc, int K)
{
    __shared__ unsigned As[2][16][136];
    __shared__ unsigned Bs[2][16][136];

    const int t    = threadIdx.x;
    const int lane = t & 31;
    const int wid  = t >> 5;
    const int wm   = (wid & 3) * 32;
    const int wn   = (wid >> 2) * 64;
    const int bx   = blockIdx.x * 128;
    const int by   = blockIdx.y * 128;
    const int tg   = lane & 3;
    const int gp   = lane >> 2;

    float c[2][8][4] = {};
    const int NIT = K >> 4;

    float4 aReg[2];
    uint4  aRegH;
    float4 bReg[2];

    auto ldA = [&](int k0) {
        if constexpr (AHALF) {
            const __half* A = (const __half*)Av;
            int row = t >> 1, kh = (t & 1) * 8;
            int gm = by + row;
            aRegH = make_uint4(0u, 0u, 0u, 0u);
            if (gm < M) aRegH = *(const uint4*)&A[(size_t)gm * K + k0 + kh];
        } else {
            const float* A = (const float*)Av;
            #pragma unroll
            for (int i = 0; i < 2; i++) {
                int idx = t + i * 256;
                int m = idx >> 2, cc = (idx & 3) * 4;
                int gm = by + m;
                aReg[i] = (gm < M) ? *(const float4*)&A[(size_t)gm * K + k0 + cc]
                                   : make_float4(0.f, 0.f, 0.f, 0.f);
            }
        }
    };
    auto ldB = [&](int k0) {
        #pragma unroll
        for (int i = 0; i < 2; i++) {
            int idx = t + i * 256;
            int kk = idx >> 5, n4 = idx & 31;
            int col = bx + n4 * 4;
            bReg[i] = (col < Nc) ? *(const float4*)&B[(size_t)(k0 + kk) * Nc + col]
                                 : make_float4(0.f, 0.f, 0.f, 0.f);
        }
    };
    auto stA = [&](int buf) {
        if constexpr (AHALF) {
            int row = t >> 1, kh = (t & 1) * 8;
            const __half2* hp = (const __half2*)&aRegH;
            #pragma unroll
            for (int j = 0; j < 4; j++) {
                float2 f = __half22float2(hp[j]);
                As[buf][kh + 2 * j][row]     = f2tf(f.x);
                As[buf][kh + 2 * j + 1][row] = f2tf(f.y);
            }
        } else {
            #pragma unroll
            for (int i = 0; i < 2; i++) {
                int idx = t + i * 256;
                int m = idx >> 2, cc = (idx & 3) * 4;
                As[buf][cc + 0][m] = f2tf(aReg[i].x);
                As[buf][cc + 1][m] = f2tf(aReg[i].y);
                As[buf][cc + 2][m] = f2tf(aReg[i].z);
                As[buf][cc + 3][m] = f2tf(aReg[i].w);
            }
        }
    };
    auto stB = [&](int buf) {
        #pragma unroll
        for (int i = 0; i < 2; i++) {
            int idx = t + i * 256;
            int kk = idx >> 5, n4 = idx & 31;
            Bs[buf][kk][n4 * 4 + 0] = f2tf(bReg[i].x);
            Bs[buf][kk][n4 * 4 + 1] = f2tf(bReg[i].y);
            Bs[buf][kk][n4 * 4 + 2] = f2tf(bReg[i].z);
            Bs[buf][kk][n4 * 4 + 3] = f2tf(bReg[i].w);
        }
    };

    ldA(0); ldB(0);
    stA(0); stB(0);

    int p = 0;
    for (int it = 0; it < NIT; it++) {
        __syncthreads();
        if (it + 1 < NIT) { ldA((it + 1) * 16); ldB((it + 1) * 16); }
        #pragma unroll
        for (int k8i = 0; k8i < 2; k8i++) {
            int kb = k8i * 8;
            unsigned a[2][4];
            #pragma unroll
            for (int mt = 0; mt < 2; mt++) {
                int m = wm + mt * 16 + gp;
                a[mt][0] = As[p][kb + tg][m];
                a[mt][1] = As[p][kb + tg][m + 8];
                a[mt][2] = As[p][kb + tg + 4][m];
                a[mt][3] = As[p][kb + tg + 4][m + 8];
            }
            #pragma unroll
            for (int nt = 0; nt < 8; nt++) {
                int n = wn + nt * 8 + gp;
                unsigned b0 = Bs[p][kb + tg][n];
                unsigned b1 = Bs[p][kb + tg + 4][n];
                #pragma unroll
                for (int mt = 0; mt < 2; mt++)
                    mma_tf32(c[mt][nt][0], c[mt][nt][1], c[mt][nt][2], c[mt][nt][3],
                             a[mt][0], a[mt][1], a[mt][2], a[mt][3], b0, b1);
            }
        }
        if (it + 1 < NIT) { int q = p ^ 1; stA(q); stB(q); }
        p ^= 1;
    }

    #pragma unroll
    for (int mt = 0; mt < 2; mt++) {
        int r0 = by + wm + mt * 16 + gp;
        #pragma unroll
        for (int nt = 0; nt < 8; nt++) {
            int col = bx + wn + nt * 8 + 2 * tg;
            if (col >= Nc) continue;
            if constexpr (CHALF) {
                __half* C = (__half*)Cv;
                if (r0 < M) {
                    __half2 h = __floats2half2_rn(c[mt][nt][0], c[mt][nt][1]);
                    *(__half2*)&C[(size_t)r0 * Nc + col] = h;
                }
                if (r0 + 8 < M) {
                    __half2 h = __floats2half2_rn(c[mt][nt][2], c[mt][nt][3]);
                    *(__half2*)&C[(size_t)(r0 + 8) * Nc + col] = h;
                }
            } else {
                float* C = (float*)Cv;
                float b0 = bias ? bias[col] : 0.f;
                float b1 = bias ? bias[col + 1] : 0.f;
                if (r0 < M)
                    *(float2*)&C[(size_t)r0 * Nc + col] =
                        make_float2(c[mt][nt][0] + b0, c[mt][nt][1] + b1);
                if (r0 + 8 < M)
                    *(float2*)&C[(size_t)(r0 + 8) * Nc + col] =
                        make_float2(c[mt][nt][2] + b0, c[mt][nt][3] + b1);
            }
        }
    }
}

// ---------------- alpha: 1 warp per node, all 4 heads ----------------
// lane owns 8 halves: head = lane>>3, feats (lane&7)*8 .. +7 within head.
__global__ __launch_bounds__(256) void alpha_kernel(
    const __half* __restrict__ h, const float* __restrict__ att_s,
    const float* __restrict__ att_d, float* __restrict__ asrc,
    float* __restrict__ adst)
{
    int n = (blockIdx.x * blockDim.x + threadIdx.x) >> 5;
    int lane = threadIdx.x & 31;
    if (n >= NN) return;
    int off = lane * 8;                           // == (lane>>3)*64 + (lane&7)*8
    uint4 raw = *(const uint4*)&h[(size_t)n * 256 + off];
    float4 a0 = *(const float4*)&att_s[off];
    float4 a1 = *(const float4*)&att_s[off + 4];
    float4 d0 = *(const float4*)&att_d[off];
    float4 d1 = *(const float4*)&att_d[off + 4];
    const __half2* hp = (const __half2*)&raw;
    float2 f0 = __half22float2(hp[0]);
    float2 f1 = __half22float2(hp[1]);
    float2 f2 = __half22float2(hp[2]);
    float2 f3 = __half22float2(hp[3]);
    float s1 = f0.x * a0.x + f0.y * a0.y + f1.x * a0.z + f1.y * a0.w
             + f2.x * a1.x + f2.y * a1.y + f3.x * a1.z + f3.y * a1.w;
    float s2 = f0.x * d0.x + f0.y * d0.y + f1.x * d0.z + f1.y * d0.w
             + f2.x * d1.x + f2.y * d1.y + f3.x * d1.z + f3.y * d1.w;
    // reduce within 8-lane head groups
    #pragma unroll
    for (int o = 1; o < 8; o <<= 1) {
        s1 += __shfl_xor_sync(0xffffffffu, s1, o);
        s2 += __shfl_xor_sync(0xffffffffu, s2, o);
    }
    if ((lane & 7) == 0) {
        int hh = lane >> 3;
        asrc[n * 4 + hh] = s1;
        adst[n * 4 + hh] = s2;
    }
}

// ---------------- edge weights + per-node inverse denominators ----------------
__global__ __launch_bounds__(256) void weight_kernel(
    const float* __restrict__ asrc, const float* __restrict__ adst,
    float* __restrict__ w, float* __restrict__ sinv)
{
    int n = (blockIdx.x * blockDim.x + threadIdx.x) >> 5;
    int lane = threadIdx.x & 31;
    if (n >= NN) return;
    int r0 = g_row[n], deg = g_row[n + 1] - r0;
    float4 ad = *(const float4*)&adst[n * 4];
    float d0 = 0.f, d1 = 0.f, d2 = 0.f, d3 = 0.f;
    for (int j = lane; j < deg; j += 32) {
        int s = g_csr_src[r0 + j];
        float4 as = *(const float4*)&asrc[s * 4];
        float e0 = as.x + ad.x; e0 = e0 > 0.f ? e0 : 0.2f * e0;
        float e1 = as.y + ad.y; e1 = e1 > 0.f ? e1 : 0.2f * e1;
        float e2 = as.z + ad.z; e2 = e2 > 0.f ? e2 : 0.2f * e2;
        float e3 = as.w + ad.w; e3 = e3 > 0.f ? e3 : 0.2f * e3;
        float4 wv = make_float4(__expf(e0), __expf(e1), __expf(e2), __expf(e3));
        *(float4*)&w[(size_t)(r0 + j) * 4] = wv;
        d0 += wv.x; d1 += wv.y; d2 += wv.z; d3 += wv.w;
    }
    #pragma unroll
    for (int o = 16; o; o >>= 1) {
        d0 += __shfl_xor_sync(0xffffffffu, d0, o);
        d1 += __shfl_xor_sync(0xffffffffu, d1, o);
        d2 += __shfl_xor_sync(0xffffffffu, d2, o);
        d3 += __shfl_xor_sync(0xffffffffu, d3, o);
    }
    if (lane == 0) {
        float4 iv = make_float4(1.f / d0, 1.f / d1, 1.f / d2, 1.f / d3);
        *(float4*)&sinv[n * 4] = iv;
    }
}

// ---------------- gather core: 32 threads/node, 16B loads, unroll 4 ----------------
// lane owns 8 features (head = lane>>3). acc[8] in registers.
__device__ __forceinline__ void gather_node32(
    int n, int lane, const __half* __restrict__ hfeat,
    const float* __restrict__ w, const float* __restrict__ sinv,
    float acc[8])
{
    int r0 = g_row[n], deg = g_row[n + 1] - r0;
    int h = lane >> 3;
    const __half* fp = hfeat + lane * 8;
    #pragma unroll
    for (int i = 0; i < 8; i++) acc[i] = 0.f;
    int j = 0;
    for (; j + 4 <= deg; j += 4) {
        int s[4]; float wv[4]; uint4 raw[4];
        #pragma unroll
        for (int u = 0; u < 4; u++) {
            s[u]  = __ldg(&g_csr_src[r0 + j + u]);
            wv[u] = __ldg(&w[(size_t)(r0 + j + u) * 4 + h]);
        }
        #pragma unroll
        for (int u = 0; u < 4; u++)
            raw[u] = *(const uint4*)&fp[(size_t)s[u] * 256];
        #pragma unroll
        for (int u = 0; u < 4; u++) {
            const __half2* hp = (const __half2*)&raw[u];
            #pragma unroll
            for (int k = 0; k < 4; k++) {
                float2 f = __half22float2(hp[k]);
                acc[2 * k]     = fmaf(wv[u], f.x, acc[2 * k]);
                acc[2 * k + 1] = fmaf(wv[u], f.y, acc[2 * k + 1]);
            }
        }
    }
    for (; j < deg; j++) {
        int s = __ldg(&g_csr_src[r0 + j]);
        float wv = __ldg(&w[(size_t)(r0 + j) * 4 + h]);
        uint4 raw = *(const uint4*)&fp[(size_t)s * 256];
        const __half2* hp = (const __half2*)&raw;
        #pragma unroll
        for (int k = 0; k < 4; k++) {
            float2 f = __half22float2(hp[k]);
            acc[2 * k]     = fmaf(wv, f.x, acc[2 * k]);
            acc[2 * k + 1] = fmaf(wv, f.y, acc[2 * k + 1]);
        }
    }
    float sc = sinv[n * 4 + h];
    #pragma unroll
    for (int i = 0; i < 8; i++) acc[i] *= sc;
}

// ---------------- layer 1: gather + bias + LN(256) + ELU -> fp16 ----------------
// 256 threads = 8 nodes/block, pure warp-level LN.
__global__ __launch_bounds__(256) void agg1_kernel(
    const __half* __restrict__ hfeat, const float* __restrict__ w,
    const float* __restrict__ sinv, const float* __restrict__ bias,
    const float* __restrict__ g, const float* __restrict__ b,
    __half* __restrict__ out)
{
    int tid = threadIdx.x;
    int grp = tid >> 5, lane = tid & 31;
    int n = blockIdx.x * 8 + grp;

    float acc[8];
    gather_node32(n, lane, hfeat, w, sinv, acc);

    int off = lane * 8;
    float4 bv0 = *(const float4*)&bias[off];
    float4 bv1 = *(const float4*)&bias[off + 4];
    float v[8];
    v[0] = acc[0] + bv0.x; v[1] = acc[1] + bv0.y;
    v[2] = acc[2] + bv0.z; v[3] = acc[3] + bv0.w;
    v[4] = acc[4] + bv1.x; v[5] = acc[5] + bv1.y;
    v[6] = acc[6] + bv1.z; v[7] = acc[7] + bv1.w;

    float t = 0.f;
    #pragma unroll
    for (int i = 0; i < 8; i++) t += v[i];
    #pragma unroll
    for (int o = 16; o; o >>= 1) t += __shfl_xor_sync(0xffffffffu, t, o);
    float mu = t * (1.f / 256.f);
    float t2 = 0.f;
    #pragma unroll
    for (int i = 0; i < 8; i++) { float d = v[i] - mu; t2 += d * d; }
    #pragma unroll
    for (int o = 16; o; o >>= 1) t2 += __shfl_xor_sync(0xffffffffu, t2, o);
    float rs = rsqrtf(t2 * (1.f / 256.f) + 1e-5f);

    float4 gv0 = *(const float4*)&g[off];
    float4 gv1 = *(const float4*)&g[off + 4];
    float4 bb0 = *(const float4*)&b[off];
    float4 bb1 = *(const float4*)&b[off + 4];
    float gg[8] = {gv0.x, gv0.y, gv0.z, gv0.w, gv1.x, gv1.y, gv1.z, gv1.w};
    float bz[8] = {bb0.x, bb0.y, bb0.z, bb0.w, bb1.x, bb1.y, bb1.z, bb1.w};

    __half2 o4[4];
    #pragma unroll
    for (int k = 0; k < 4; k++) {
        float y0 = (v[2 * k] - mu) * rs * gg[2 * k] + bz[2 * k];
        float y1 = (v[2 * k + 1] - mu) * rs * gg[2 * k + 1] + bz[2 * k + 1];
        y0 = y0 > 0.f ? y0 : expm1f(y0);
        y1 = y1 > 0.f ? y1 : expm1f(y1);
        o4[k] = __floats2half2_rn(y0, y1);
    }
    *(uint4*)&out[(size_t)n * 256 + off] = *(uint4*)o4;
}

// ---------- layer 2: gather + head-mean + bias + LN(64) + res + ELU ----------
__global__ __launch_bounds__(256) void agg2_kernel(
    const __half* __restrict__ hfeat, const float* __restrict__ w,
    const float* __restrict__ sinv, const float* __restrict__ bias,
    const float* __restrict__ g, const float* __restrict__ b,
    const float* __restrict__ idn, float* __restrict__ out)
{
    int tid = threadIdx.x;
    int grp = tid >> 5, lane = tid & 31;
    int n = blockIdx.x * 8 + grp;

    float acc[8];
    gather_node32(n, lane, hfeat, w, sinv, acc);

    // head mean via shuffles: lanes 0..7 end up with features (lane*8..+7)
    int base = lane & 7;
    float m[8];
    #pragma unroll
    for (int i = 0; i < 8; i++) {
        float v0 = __shfl_sync(0xffffffffu, acc[i], base);
        float v1 = __shfl_sync(0xffffffffu, acc[i], base + 8);
        float v2 = __shfl_sync(0xffffffffu, acc[i], base + 16);
        float v3 = __shfl_sync(0xffffffffu, acc[i], base + 24);
        m[i] = 0.25f * (v0 + v1 + v2 + v3);
    }

    if (lane < 8) {
        int off = lane * 8;
        float4 bv0 = *(const float4*)&bias[off];
        float4 bv1 = *(const float4*)&bias[off + 4];
        float bvv[8] = {bv0.x, bv0.y, bv0.z, bv0.w, bv1.x, bv1.y, bv1.z, bv1.w};
        #pragma unroll
        for (int i = 0; i < 8; i++) m[i] += bvv[i];

        float t = 0.f;
        #pragma unroll
        for (int i = 0; i < 8; i++) t += m[i];
        #pragma unroll
        for (int o = 1; o < 8; o <<= 1) t += __shfl_xor_sync(0x000000ffu, t, o);
        float mu = t * (1.f / 64.f);
        float t2 = 0.f;
        #pragma unroll
        for (int i = 0; i < 8; i++) { float d = m[i] - mu; t2 += d * d; }
        #pragma unroll
        for (int o = 1; o < 8; o <<= 1) t2 += __shfl_xor_sync(0x000000ffu, t2, o);
        float rs = rsqrtf(t2 * (1.f / 64.f) + 1e-5f);

        float4 gv0 = *(const float4*)&g[off];
        float4 gv1 = *(const float4*)&g[off + 4];
        float4 bb0 = *(const float4*)&b[off];
        float4 bb1 = *(const float4*)&b[off + 4];
        float4 iv0 = *(const float4*)&idn[(size_t)n * 64 + off];
        float4 iv1 = *(const float4*)&idn[(size_t)n * 64 + off + 4];
        float gg[8] = {gv0.x, gv0.y, gv0.z, gv0.w, gv1.x, gv1.y, gv1.z, gv1.w};
        float bz[8] = {bb0.x, bb0.y, bb0.z, bb0.w, bb1.x, bb1.y, bb1.z, bb1.w};
        float iv[8] = {iv0.x, iv0.y, iv0.z, iv0.w, iv1.x, iv1.y, iv1.z, iv1.w};

        float y[8];
        #pragma unroll
        for (int i = 0; i < 8; i++) {
            float yy = (m[i] - mu) * rs * gg[i] + bz[i] + iv[i];
            y[i] = yy > 0.f ? yy : expm1f(yy);
        }
        *(float4*)&out[(size_t)n * 64 + off]     = make_float4(y[0], y[1], y[2], y[3]);
        *(float4*)&out[(size_t)n * 64 + off + 4] = make_float4(y[4], y[5], y[6], y[7]);
    }
}

// ---------------- launcher ----------------
extern "C" void kernel_launch(void* const* d_in, const int* in_sizes, int n_in,
                              void* d_out, int out_size) {
    const float* x        = (const float*)d_in[0];
    const void*  ei       = d_in[1];
    const float* W1       = (const float*)d_in[2];
    const float* att_src1 = (const float*)d_in[3];
    const float* att_dst1 = (const float*)d_in[4];
    const float* bias1    = (const float*)d_in[5];
    const float* g1       = (const float*)d_in[6];
    const float* b1       = (const float*)d_in[7];
    const float* W2       = (const float*)d_in[8];
    const float* att_src2 = (const float*)d_in[9];
    const float* att_dst2 = (const float*)d_in[10];
    const float* bias2    = (const float*)d_in[11];
    const float* g2       = (const float*)d_in[12];
    const float* b2       = (const float*)d_in[13];
    const float* Wres     = (const float*)d_in[14];
    const float* bres     = (const float*)d_in[15];
    float* out = (float*)d_out;

    __half *p_h1, *p_h1a, *p_h2;
    float *p_id, *p_asrc, *p_adst, *p_w, *p_sinv;
    cudaGetSymbolAddress((void**)&p_h1,   g_h1);
    cudaGetSymbolAddress((void**)&p_h1a,  g_h1a);
    cudaGetSymbolAddress((void**)&p_h2,   g_h2);
    cudaGetSymbolAddress((void**)&p_id,   g_id);
    cudaGetSymbolAddress((void**)&p_asrc, g_asrc);
    cudaGetSymbolAddress((void**)&p_adst, g_adst);
    cudaGetSymbolAddress((void**)&p_w,    g_w);
    cudaGetSymbolAddress((void**)&p_sinv, g_sinv);

    dim3 blk(256);

    // CSR build start
    detect_kernel<<<1, 256>>>((const unsigned int*)ei);
    zero_deg_kernel<<<NB, 256>>>();
    count_kernel<<<(ET + 255) / 256, 256>>>(ei);
    // #4: layer-1 projection (profiling slot): x(fp32) @ W1 -> h1 (fp16)
    {
        dim3 grid(HC1 / 128, (NN + 127) / 128);
        sgemm_tf32_t<false, true><<<grid, blk>>>(x, W1, nullptr, p_h1, NN, HC1, INF_);
    }
    // rest of CSR build
    bsum_kernel<<<NB, 256>>>();
    bscan_kernel<<<1, 256>>>();
    rowscan_kernel<<<NB, 256>>>();
    fill_kernel<<<(ET + 255) / 256, 256>>>(ei);
    // residual: x(fp32) @ Wres + bres -> id (fp32)
    {
        dim3 grid(1, (NN + 127) / 128);
        sgemm_tf32_t<false, false><<<grid, blk>>>(x, Wres, bres, p_id, NN, 64, INF_);
    }

    alpha_kernel<<<(NN * 32 + 255) / 256, 256>>>(p_h1, att_src1, att_dst1, p_asrc, p_adst);
    weight_kernel<<<(NN * 32 + 255) / 256, 256>>>(p_asrc, p_adst, p_w, p_sinv);
    agg1_kernel<<<NN / 8, 256>>>(p_h1, p_w, p_sinv, bias1, g1, b1, p_h1a);

    // layer-2 projection: h1a(fp16) @ W2 -> h2 (fp16)
    {
        dim3 grid(HC2 / 128, (NN + 127) / 128);
        sgemm_tf32_t<true, true><<<grid, blk>>>(p_h1a, W2, nullptr, p_h2, NN, HC2, HC1);
    }
    alpha_kernel<<<(NN * 32 + 255) / 256, 256>>>(p_h2, att_src2, att_dst2, p_asrc, p_adst);
    weight_kernel<<<(NN * 32 + 255) / 256, 256>>>(p_asrc, p_adst, p_w, p_sinv);
    agg2_kernel<<<NN / 8, 256>>>(p_h2, p_w, p_sinv, bias2, g2, b2, p_id, out);
}

// round 11
// speedup vs baseline: 7.0976x; 1.0994x over previous
#include <cuda_runtime.h>
#include <cuda_bf16.h>
#include <cuda_fp16.h>
#include <math.h>

// Problem constants
#define NN 50000
#define EE 800000
#define ET 850000            // EE + NN self loops
#define HH 4
#define HC1 256
#define CC2 64
#define HC2 256
#define INF_ 128
#define NB 196               // ceil(NN/256)

// ---------------- scratch (device globals; no allocation) ----------------
__device__ __align__(16) __half g_h1[(size_t)NN * HC1];
__device__ __align__(16) __half g_h1a[(size_t)NN * HC1];
__device__ __align__(16) __half g_h2[(size_t)NN * HC2];
__device__ __align__(16) float  g_id[(size_t)NN * CC2];
__device__ __align__(16) float  g_asrc[NN * HH];
__device__ __align__(16) float  g_adst[NN * HH];
__device__ int   g_deg[NN];
__device__ int   g_row[NN + 1];
__device__ int   g_cursor[NN];
__device__ int   g_csr_src[ET];
__device__ int   g_bsum[NB];
__device__ int   g_boff[NB];
__device__ int   g_is64;

// ---------------- edge index dtype detection ----------------
__global__ void detect_kernel(const unsigned int* __restrict__ words) {
    __shared__ int any;
    if (threadIdx.x == 0) any = 0;
    __syncthreads();
    for (int i = threadIdx.x; i < 4096; i += blockDim.x)
        if (words[2 * i + 1] != 0u) any = 1;
    __syncthreads();
    if (threadIdx.x == 0) g_is64 = any ? 0 : 1;
}

__device__ __forceinline__ void load_edge(const void* ei, int e, int& src, int& dst) {
    if (e < EE) {
        if (g_is64) {
            const long long* p = (const long long*)ei;
            src = (int)p[e];
            dst = (int)p[EE + e];
        } else {
            const int* p = (const int*)ei;
            src = p[e];
            dst = p[EE + e];
        }
    } else {
        src = dst = e - EE;
    }
}

// ---------------- CSR build ----------------
__global__ void zero_deg_kernel() {
    int i = blockIdx.x * blockDim.x + threadIdx.x;
    if (i < NN) g_deg[i] = 0;
}

__global__ void count_kernel(const void* __restrict__ ei) {
    int e = blockIdx.x * blockDim.x + threadIdx.x;
    if (e >= ET) return;
    int s, d;
    load_edge(ei, e, s, d);
    atomicAdd(&g_deg[d], 1);
}

__global__ __launch_bounds__(256) void bsum_kernel() {
    __shared__ int sh[256];
    int i = blockIdx.x * 256 + threadIdx.x;
    sh[threadIdx.x] = (i < NN) ? g_deg[i] : 0;
    __syncthreads();
    for (int o = 128; o; o >>= 1) {
        if (threadIdx.x < o) sh[threadIdx.x] += sh[threadIdx.x + o];
        __syncthreads();
    }
    if (threadIdx.x == 0) g_bsum[blockIdx.x] = sh[0];
}

__global__ __launch_bounds__(256) void bscan_kernel() {
    __shared__ int sh[256];
    int tid = threadIdx.x;
    int v = (tid < NB) ? g_bsum[tid] : 0;
    sh[tid] = v;
    __syncthreads();
    for (int o = 1; o < 256; o <<= 1) {
        int t = 0;
        if (tid >= o) t = sh[tid - o];
        __syncthreads();
        sh[tid] += t;
        __syncthreads();
    }
    if (tid < NB) g_boff[tid] = sh[tid] - v;   // exclusive
    if (tid == 0) g_row[NN] = ET;
}

__global__ __launch_bounds__(256) void rowscan_kernel() {
    __shared__ int sh[256];
    int tid = threadIdx.x;
    int i = blockIdx.x * 256 + tid;
    int v = (i < NN) ? g_deg[i] : 0;
    sh[tid] = v;
    __syncthreads();
    for (int o = 1; o < 256; o <<= 1) {
        int t = 0;
        if (tid >= o) t = sh[tid - o];
        __syncthreads();
        sh[tid] += t;
        __syncthreads();
    }
    if (i < NN) {
        int r = g_boff[blockIdx.x] + sh[tid] - v;
        g_row[i] = r;
        g_cursor[i] = r;
    }
}

__global__ void fill_kernel(const void* __restrict__ ei) {
    int e = blockIdx.x * blockDim.x + threadIdx.x;
    if (e >= ET) return;
    int s, d;
    load_edge(ei, e, s, d);
    int pos = atomicAdd(&g_cursor[d], 1);
    g_csr_src[pos] = s;
}

// ---------------- tf32 helpers ----------------
__device__ __forceinline__ unsigned f2tf(float f) {
    unsigned r;
    asm("cvt.rna.tf32.f32 %0, %1;" : "=r"(r) : "f"(f));
    return r;
}

__device__ __forceinline__ void mma_tf32(
    float& c0, float& c1, float& c2, float& c3,
    unsigned a0, unsigned a1, unsigned a2, unsigned a3,
    unsigned b0, unsigned b1)
{
    asm volatile(
        "mma.sync.aligned.m16n8k8.row.col.f32.tf32.tf32.f32 "
        "{%0,%1,%2,%3}, {%4,%5,%6,%7}, {%8,%9}, {%0,%1,%2,%3};"
        : "+f"(c0), "+f"(c1), "+f"(c2), "+f"(c3)
        : "r"(a0), "r"(a1), "r"(a2), "r"(a3), "r"(b0), "r"(b1));
}

// ---------------- tf32 GEMM core (one output tile) ----------------
// A fp32 or fp16; C fp16 or fp32(+bias).
template<bool AHALF, bool CHALF>
__device__ __forceinline__ void gemm_tile(
    const void* __restrict__ Av, const float* __restrict__ B,
    const float* __restrict__ bias, void* __restrict__ Cv,
    int M, int Nc, int K, int bx, int by,
    unsigned (*As)[16][136], unsigned (*Bs)[16][136])
{
    const int t    = threadIdx.x;
    const int lane = t & 31;
    const int wid  = t >> 5;
    const int wm   = (wid & 3) * 32;
    const int wn   = (wid >> 2) * 64;
    const int tg   = lane & 3;
    const int gp   = lane >> 2;

    float c[2][8][4] = {};
    const int NIT = K >> 4;

    float4 aReg[2];
    uint4  aRegH;
    float4 bReg[2];

    auto ldA = [&](int k0) {
        if constexpr (AHALF) {
            const __half* A = (const __half*)Av;
            int row = t >> 1, kh = (t & 1) * 8;
            int gm = by + row;
            aRegH = make_uint4(0u, 0u, 0u, 0u);
            if (gm < M) aRegH = *(const uint4*)&A[(size_t)gm * K + k0 + kh];
        } else {
            const float* A = (const float*)Av;
            #pragma unroll
            for (int i = 0; i < 2; i++) {
                int idx = t + i * 256;
                int m = idx >> 2, cc = (idx & 3) * 4;
                int gm = by + m;
                aReg[i] = (gm < M) ? *(const float4*)&A[(size_t)gm * K + k0 + cc]
                                   : make_float4(0.f, 0.f, 0.f, 0.f);
            }
        }
    };
    auto ldB = [&](int k0) {
        #pragma unroll
        for (int i = 0; i < 2; i++) {
            int idx = t + i * 256;
            int kk = idx >> 5, n4 = idx & 31;
            int col = bx + n4 * 4;
            bReg[i] = (col < Nc) ? *(const float4*)&B[(size_t)(k0 + kk) * Nc + col]
                                 : make_float4(0.f, 0.f, 0.f, 0.f);
        }
    };
    auto stA = [&](int buf) {
        if constexpr (AHALF) {
            int row = t >> 1, kh = (t & 1) * 8;
            const __half2* hp = (const __half2*)&aRegH;
            #pragma unroll
            for (int j = 0; j < 4; j++) {
                float2 f = __half22float2(hp[j]);
                As[buf][kh + 2 * j][row]     = f2tf(f.x);
                As[buf][kh + 2 * j + 1][row] = f2tf(f.y);
            }
        } else {
            #pragma unroll
            for (int i = 0; i < 2; i++) {
                int idx = t + i * 256;
                int m = idx >> 2, cc = (idx & 3) * 4;
                As[buf][cc + 0][m] = f2tf(aReg[i].x);
                As[buf][cc + 1][m] = f2tf(aReg[i].y);
                As[buf][cc + 2][m] = f2tf(aReg[i].z);
                As[buf][cc + 3][m] = f2tf(aReg[i].w);
            }
        }
    };
    auto stB = [&](int buf) {
        #pragma unroll
        for (int i = 0; i < 2; i++) {
            int idx = t + i * 256;
            int kk = idx >> 5, n4 = idx & 31;
            Bs[buf][kk][n4 * 4 + 0] = f2tf(bReg[i].x);
            Bs[buf][kk][n4 * 4 + 1] = f2tf(bReg[i].y);
            Bs[buf][kk][n4 * 4 + 2] = f2tf(bReg[i].z);
            Bs[buf][kk][n4 * 4 + 3] = f2tf(bReg[i].w);
        }
    };

    ldA(0); ldB(0);
    stA(0); stB(0);

    int p = 0;
    for (int it = 0; it < NIT; it++) {
        __syncthreads();
        if (it + 1 < NIT) { ldA((it + 1) * 16); ldB((it + 1) * 16); }
        #pragma unroll
        for (int k8i = 0; k8i < 2; k8i++) {
            int kb = k8i * 8;
            unsigned a[2][4];
            #pragma unroll
            for (int mt = 0; mt < 2; mt++) {
                int m = wm + mt * 16 + gp;
                a[mt][0] = As[p][kb + tg][m];
                a[mt][1] = As[p][kb + tg][m + 8];
                a[mt][2] = As[p][kb + tg + 4][m];
                a[mt][3] = As[p][kb + tg + 4][m + 8];
            }
            #pragma unroll
            for (int nt = 0; nt < 8; nt++) {
                int n = wn + nt * 8 + gp;
                unsigned b0 = Bs[p][kb + tg][n];
                unsigned b1 = Bs[p][kb + tg + 4][n];
                #pragma unroll
                for (int mt = 0; mt < 2; mt++)
                    mma_tf32(c[mt][nt][0], c[mt][nt][1], c[mt][nt][2], c[mt][nt][3],
                             a[mt][0], a[mt][1], a[mt][2], a[mt][3], b0, b1);
            }
        }
        if (it + 1 < NIT) { int q = p ^ 1; stA(q); stB(q); }
        p ^= 1;
    }

    #pragma unroll
    for (int mt = 0; mt < 2; mt++) {
        int r0 = by + wm + mt * 16 + gp;
        #pragma unroll
        for (int nt = 0; nt < 8; nt++) {
            int col = bx + wn + nt * 8 + 2 * tg;
            if (col >= Nc) continue;
            if constexpr (CHALF) {
                __half* C = (__half*)Cv;
                if (r0 < M) {
                    __half2 h = __floats2half2_rn(c[mt][nt][0], c[mt][nt][1]);
                    *(__half2*)&C[(size_t)r0 * Nc + col] = h;
                }
                if (r0 + 8 < M) {
                    __half2 h = __floats2half2_rn(c[mt][nt][2], c[mt][nt][3]);
                    *(__half2*)&C[(size_t)(r0 + 8) * Nc + col] = h;
                }
            } else {
                float* C = (float*)Cv;
                float b0 = bias ? bias[col] : 0.f;
                float b1 = bias ? bias[col + 1] : 0.f;
                if (r0 < M)
                    *(float2*)&C[(size_t)r0 * Nc + col] =
                        make_float2(c[mt][nt][0] + b0, c[mt][nt][1] + b1);
                if (r0 + 8 < M)
                    *(float2*)&C[(size_t)(r0 + 8) * Nc + col] =
                        make_float2(c[mt][nt][2] + b0, c[mt][nt][3] + b1);
            }
        }
    }
}

// Fused layer-1 + residual GEMM: blocks x=0,1 -> h1 (fp16); x=2 -> id (fp32 + bias)
__global__ __launch_bounds__(256, 2) void gemm1_fused(
    const float* __restrict__ x, const float* __restrict__ W1,
    const float* __restrict__ Wres, const float* __restrict__ bres,
    __half* __restrict__ h1, float* __restrict__ idn)
{
    __shared__ unsigned As[2][16][136];
    __shared__ unsigned Bs[2][16][136];
    int by = blockIdx.y * 128;
    if (blockIdx.x < 2) {
        gemm_tile<false, true>(x, W1, nullptr, h1, NN, HC1, INF_,
                               blockIdx.x * 128, by, As, Bs);
    } else {
        gemm_tile<false, false>(x, Wres, bres, idn, NN, CC2, INF_,
                                0, by, As, Bs);
    }
}

// Layer-2 GEMM: h1a (fp16) @ W2 -> h2 (fp16)
__global__ __launch_bounds__(256, 2) void gemm2_kernel(
    const __half* __restrict__ h1a, const float* __restrict__ W2,
    __half* __restrict__ h2)
{
    __shared__ unsigned As[2][16][136];
    __shared__ unsigned Bs[2][16][136];
    gemm_tile<true, true>(h1a, W2, nullptr, h2, NN, HC2, HC1,
                          blockIdx.x * 128, blockIdx.y * 128, As, Bs);
}

// ---------------- alpha: 1 warp per node, all 4 heads ----------------
__global__ __launch_bounds__(256) void alpha_kernel(
    const __half* __restrict__ h, const float* __restrict__ att_s,
    const float* __restrict__ att_d, float* __restrict__ asrc,
    float* __restrict__ adst)
{
    int n = (blockIdx.x * blockDim.x + threadIdx.x) >> 5;
    int lane = threadIdx.x & 31;
    if (n >= NN) return;
    int off = lane * 8;
    uint4 raw = *(const uint4*)&h[(size_t)n * 256 + off];
    float4 a0 = *(const float4*)&att_s[off];
    float4 a1 = *(const float4*)&att_s[off + 4];
    float4 d0 = *(const float4*)&att_d[off];
    float4 d1 = *(const float4*)&att_d[off + 4];
    const __half2* hp = (const __half2*)&raw;
    float2 f0 = __half22float2(hp[0]);
    float2 f1 = __half22float2(hp[1]);
    float2 f2 = __half22float2(hp[2]);
    float2 f3 = __half22float2(hp[3]);
    float s1 = f0.x * a0.x + f0.y * a0.y + f1.x * a0.z + f1.y * a0.w
             + f2.x * a1.x + f2.y * a1.y + f3.x * a1.z + f3.y * a1.w;
    float s2 = f0.x * d0.x + f0.y * d0.y + f1.x * d0.z + f1.y * d0.w
             + f2.x * d1.x + f2.y * d1.y + f3.x * d1.z + f3.y * d1.w;
    #pragma unroll
    for (int o = 1; o < 8; o <<= 1) {
        s1 += __shfl_xor_sync(0xffffffffu, s1, o);
        s2 += __shfl_xor_sync(0xffffffffu, s2, o);
    }
    if ((lane & 7) == 0) {
        int hh = lane >> 3;
        asrc[n * 4 + hh] = s1;
        adst[n * 4 + hh] = s2;
    }
}

// ------- fused gather: softmax weights computed inline, unroll 8 -------
// 32 threads/node; lane owns 8 features of head h=lane>>3.
// Each lane walks ALL edges, computes its head's weight inline, and
// accumulates its own denominator (identical across the 8-lane group).
__device__ __forceinline__ void gather_node32f(
    int n, int lane, const __half* __restrict__ hfeat,
    const float* __restrict__ asrc, const float* __restrict__ adst,
    float acc[8])
{
    int r0 = g_row[n], deg = g_row[n + 1] - r0;
    int h = lane >> 3;
    float ad = __ldg(&adst[n * 4 + h]);
    const __half* fp = hfeat + lane * 8;
    #pragma unroll
    for (int i = 0; i < 8; i++) acc[i] = 0.f;
    float dsum = 0.f;
    int j = 0;
    for (; j + 8 <= deg; j += 8) {
        int s[8]; float wv[8]; uint4 raw[8];
        #pragma unroll
        for (int u = 0; u < 8; u++)
            s[u] = __ldg(&g_csr_src[r0 + j + u]);
        #pragma unroll
        for (int u = 0; u < 8; u++) {
            raw[u] = *(const uint4*)&fp[(size_t)s[u] * 256];
            float e = __ldg(&asrc[s[u] * 4 + h]) + ad;
            e = e > 0.f ? e : 0.2f * e;
            wv[u] = __expf(e);
        }
        #pragma unroll
        for (int u = 0; u < 8; u++) {
            dsum += wv[u];
            const __half2* hp = (const __half2*)&raw[u];
            #pragma unroll
            for (int k = 0; k < 4; k++) {
                float2 f = __half22float2(hp[k]);
                acc[2 * k]     = fmaf(wv[u], f.x, acc[2 * k]);
                acc[2 * k + 1] = fmaf(wv[u], f.y, acc[2 * k + 1]);
            }
        }
    }
    for (; j < deg; j++) {
        int s = __ldg(&g_csr_src[r0 + j]);
        float e = __ldg(&asrc[s * 4 + h]) + ad;
        e = e > 0.f ? e : 0.2f * e;
        float wv = __expf(e);
        dsum += wv;
        uint4 raw = *(const uint4*)&fp[(size_t)s * 256];
        const __half2* hp = (const __half2*)&raw;
        #pragma unroll
        for (int k = 0; k < 4; k++) {
            float2 f = __half22float2(hp[k]);
            acc[2 * k]     = fmaf(wv, f.x, acc[2 * k]);
            acc[2 * k + 1] = fmaf(wv, f.y, acc[2 * k + 1]);
        }
    }
    float sc = 1.f / dsum;
    #pragma unroll
    for (int i = 0; i < 8; i++) acc[i] *= sc;
}

// ---------------- layer 1: gather + bias + LN(256) + ELU -> fp16 ----------------
__global__ __launch_bounds__(256) void agg1_kernel(
    const __half* __restrict__ hfeat, const float* __restrict__ asrc,
    const float* __restrict__ adst, const float* __restrict__ bias,
    const float* __restrict__ g, const float* __restrict__ b,
    __half* __restrict__ out)
{
    int tid = threadIdx.x;
    int grp = tid >> 5, lane = tid & 31;
    int n = blockIdx.x * 8 + grp;

    float acc[8];
    gather_node32f(n, lane, hfeat, asrc, adst, acc);

    int off = lane * 8;
    float4 bv0 = *(const float4*)&bias[off];
    float4 bv1 = *(const float4*)&bias[off + 4];
    float v[8];
    v[0] = acc[0] + bv0.x; v[1] = acc[1] + bv0.y;
    v[2] = acc[2] + bv0.z; v[3] = acc[3] + bv0.w;
    v[4] = acc[4] + bv1.x; v[5] = acc[5] + bv1.y;
    v[6] = acc[6] + bv1.z; v[7] = acc[7] + bv1.w;

    float t = 0.f;
    #pragma unroll
    for (int i = 0; i < 8; i++) t += v[i];
    #pragma unroll
    for (int o = 16; o; o >>= 1) t += __shfl_xor_sync(0xffffffffu, t, o);
    float mu = t * (1.f / 256.f);
    float t2 = 0.f;
    #pragma unroll
    for (int i = 0; i < 8; i++) { float d = v[i] - mu; t2 += d * d; }
    #pragma unroll
    for (int o = 16; o; o >>= 1) t2 += __shfl_xor_sync(0xffffffffu, t2, o);
    float rs = rsqrtf(t2 * (1.f / 256.f) + 1e-5f);

    float4 gv0 = *(const float4*)&g[off];
    float4 gv1 = *(const float4*)&g[off + 4];
    float4 bb0 = *(const float4*)&b[off];
    float4 bb1 = *(const float4*)&b[off + 4];
    float gg[8] = {gv0.x, gv0.y, gv0.z, gv0.w, gv1.x, gv1.y, gv1.z, gv1.w};
    float bz[8] = {bb0.x, bb0.y, bb0.z, bb0.w, bb1.x, bb1.y, bb1.z, bb1.w};

    __half2 o4[4];
    #pragma unroll
    for (int k = 0; k < 4; k++) {
        float y0 = (v[2 * k] - mu) * rs * gg[2 * k] + bz[2 * k];
        float y1 = (v[2 * k + 1] - mu) * rs * gg[2 * k + 1] + bz[2 * k + 1];
        y0 = y0 > 0.f ? y0 : expm1f(y0);
        y1 = y1 > 0.f ? y1 : expm1f(y1);
        o4[k] = __floats2half2_rn(y0, y1);
    }
    *(uint4*)&out[(size_t)n * 256 + off] = *(uint4*)o4;
}

// ---------- layer 2: gather + head-mean + bias + LN(64) + res + ELU ----------
__global__ __launch_bounds__(256) void agg2_kernel(
    const __half* __restrict__ hfeat, const float* __restrict__ asrc,
    const float* __restrict__ adst, const float* __restrict__ bias,
    const float* __restrict__ g, const float* __restrict__ b,
    const float* __restrict__ idn, float* __restrict__ out)
{
    int tid = threadIdx.x;
    int grp = tid >> 5, lane = tid & 31;
    int n = blockIdx.x * 8 + grp;

    float acc[8];
    gather_node32f(n, lane, hfeat, asrc, adst, acc);

    // head mean via shuffles
    int base = lane & 7;
    float m[8];
    #pragma unroll
    for (int i = 0; i < 8; i++) {
        float v0 = __shfl_sync(0xffffffffu, acc[i], base);
        float v1 = __shfl_sync(0xffffffffu, acc[i], base + 8);
        float v2 = __shfl_sync(0xffffffffu, acc[i], base + 16);
        float v3 = __shfl_sync(0xffffffffu, acc[i], base + 24);
        m[i] = 0.25f * (v0 + v1 + v2 + v3);
    }

    if (lane < 8) {
        int off = lane * 8;
        float4 bv0 = *(const float4*)&bias[off];
        float4 bv1 = *(const float4*)&bias[off + 4];
        float bvv[8] = {bv0.x, bv0.y, bv0.z, bv0.w, bv1.x, bv1.y, bv1.z, bv1.w};
        #pragma unroll
        for (int i = 0; i < 8; i++) m[i] += bvv[i];

        float t = 0.f;
        #pragma unroll
        for (int i = 0; i < 8; i++) t += m[i];
        #pragma unroll
        for (int o = 1; o < 8; o <<= 1) t += __shfl_xor_sync(0x000000ffu, t, o);
        float mu = t * (1.f / 64.f);
        float t2 = 0.f;
        #pragma unroll
        for (int i = 0; i < 8; i++) { float d = m[i] - mu; t2 += d * d; }
        #pragma unroll
        for (int o = 1; o < 8; o <<= 1) t2 += __shfl_xor_sync(0x000000ffu, t2, o);
        float rs = rsqrtf(t2 * (1.f / 64.f) + 1e-5f);

        float4 gv0 = *(const float4*)&g[off];
        float4 gv1 = *(const float4*)&g[off + 4];
        float4 bb0 = *(const float4*)&b[off];
        float4 bb1 = *(const float4*)&b[off + 4];
        float4 iv0 = *(const float4*)&idn[(size_t)n * 64 + off];
        float4 iv1 = *(const float4*)&idn[(size_t)n * 64 + off + 4];
        float gg[8] = {gv0.x, gv0.y, gv0.z, gv0.w, gv1.x, gv1.y, gv1.z, gv1.w};
        float bz[8] = {bb0.x, bb0.y, bb0.z, bb0.w, bb1.x, bb1.y, bb1.z, bb1.w};
        float iv[8] = {iv0.x, iv0.y, iv0.z, iv0.w, iv1.x, iv1.y, iv1.z, iv1.w};

        float y[8];
        #pragma unroll
        for (int i = 0; i < 8; i++) {
            float yy = (m[i] - mu) * rs * gg[i] + bz[i] + iv[i];
            y[i] = yy > 0.f ? yy : expm1f(yy);
        }
        *(float4*)&out[(size_t)n * 64 + off]     = make_float4(y[0], y[1], y[2], y[3]);
        *(float4*)&out[(size_t)n * 64 + off + 4] = make_float4(y[4], y[5], y[6], y[7]);
    }
}

// ---------------- launcher ----------------
extern "C" void kernel_launch(void* const* d_in, const int* in_sizes, int n_in,
                              void* d_out, int out_size) {
    const float* x        = (const float*)d_in[0];
    const void*  ei       = d_in[1];
    const float* W1       = (const float*)d_in[2];
    const float* att_src1 = (const float*)d_in[3];
    const float* att_dst1 = (const float*)d_in[4];
    const float* bias1    = (const float*)d_in[5];
    const float* g1       = (const float*)d_in[6];
    const float* b1       = (const float*)d_in[7];
    const float* W2       = (const float*)d_in[8];
    const float* att_src2 = (const float*)d_in[9];
    const float* att_dst2 = (const float*)d_in[10];
    const float* bias2    = (const float*)d_in[11];
    const float* g2       = (const float*)d_in[12];
    const float* b2       = (const float*)d_in[13];
    const float* Wres     = (const float*)d_in[14];
    const float* bres     = (const float*)d_in[15];
    float* out = (float*)d_out;

    __half *p_h1, *p_h1a, *p_h2;
    float *p_id, *p_asrc, *p_adst;
    cudaGetSymbolAddress((void**)&p_h1,   g_h1);
    cudaGetSymbolAddress((void**)&p_h1a,  g_h1a);
    cudaGetSymbolAddress((void**)&p_h2,   g_h2);
    cudaGetSymbolAddress((void**)&p_id,   g_id);
    cudaGetSymbolAddress((void**)&p_asrc, g_asrc);
    cudaGetSymbolAddress((void**)&p_adst, g_adst);

    dim3 blk(256);

    // CSR build start
    detect_kernel<<<1, 256>>>((const unsigned int*)ei);
    zero_deg_kernel<<<NB, 256>>>();
    count_kernel<<<(ET + 255) / 256, 256>>>(ei);
    // #4 (profiling slot): fused layer-1 + residual projection
    {
        dim3 grid(3, (NN + 127) / 128);
        gemm1_fused<<<grid, blk>>>(x, W1, Wres, bres, p_h1, p_id);
    }
    // rest of CSR build
    bsum_kernel<<<NB, 256>>>();
    bscan_kernel<<<1, 256>>>();
    rowscan_kernel<<<NB, 256>>>();
    fill_kernel<<<(ET + 255) / 256, 256>>>(ei);

    alpha_kernel<<<(NN * 32 + 255) / 256, 256>>>(p_h1, att_src1, att_dst1, p_asrc, p_adst);
    agg1_kernel<<<NN / 8, 256>>>(p_h1, p_asrc, p_adst, bias1, g1, b1, p_h1a);

    // layer-2 projection
    {
        dim3 grid(HC2 / 128, (NN + 127) / 128);
        gemm2_kernel<<<grid, blk>>>(p_h1a, W2, p_h2);
    }
    alpha_kernel<<<(NN * 32 + 255) / 256, 256>>>(p_h2, att_src2, att_dst2, p_asrc, p_adst);
    agg2_kernel<<<NN / 8, 256>>>(p_h2, p_asrc, p_adst, bias2, g2, b2, p_id, out);
}